// round 2
// baseline (speedup 1.0000x reference)
#include <cuda_runtime.h>
#include <math.h>

#define BB 4
#define TT 2048
#define HH 512
#define VV 32000
#define FH 2048          // 4*H
#define MROWS 8192       // B*T

// ---------------- scratch (static device allocations; no cudaMalloc) ----------------
__device__ float g_xg[(size_t)MROWS * FH];     // [B*T, 4H]  67 MB
__device__ float g_enc[(size_t)MROWS * HH];    // [B*T, H]
__device__ float g_tmp[(size_t)MROWS * HH];    // tanh(enc@Wa1^T+ba1)
__device__ float g_ctx[(size_t)MROWS * HH];
__device__ float g_comb[(size_t)MROWS * HH];
__device__ float g_hbuf[2 * BB * HH];          // double-buffered h
__device__ float g_s[MROWS];
__device__ float g_e[MROWS];
__device__ float g_rden[MROWS];
__device__ unsigned g_barcnt;                  // zero-init, returns to 0 each barrier
__device__ unsigned g_bargen;                  // monotonically increasing phase

// ---------------- generic 128x128x8 fp32 GEMM:  C[m,n] = sum_k A[m,k]*Bw[n,k] (+bias[,bias2][,tanh]) ----
// AMODE: 0 = plain A (row stride K), 1 = gather rows of A via gidx (emb lookup), 2 = concat(ctx,enc) (each stride H)
template <int AMODE, bool TANH>
__global__ void __launch_bounds__(256) gemm128(
    const float* __restrict__ A, const float* __restrict__ A2,
    const int* __restrict__ gidx,
    const float* __restrict__ Bw,
    const float* __restrict__ bias, const float* __restrict__ bias2,
    float* __restrict__ C, int M, int N, int K)
{
    __shared__ float As[8][128];
    __shared__ float Bs[8][128];

    const int tid  = threadIdx.x;
    const int m0   = blockIdx.y * 128;
    const int n0   = blockIdx.x * 128;
    const int aRow = tid >> 1;
    const int aCol = (tid & 1) << 2;
    const int tx   = tid & 15;
    const int ty   = tid >> 4;

    const float* Arow0;
    const float* Arow1 = nullptr;
    if (AMODE == 1) {
        Arow0 = A + (size_t)gidx[m0 + aRow] * K;
    } else if (AMODE == 2) {
        Arow0 = A  + (size_t)(m0 + aRow) * HH;
        Arow1 = A2 + (size_t)(m0 + aRow) * HH;
    } else {
        Arow0 = A + (size_t)(m0 + aRow) * K;
    }
    const float* Brow = Bw + (size_t)(n0 + aRow) * K;

    float acc[8][8];
#pragma unroll
    for (int i = 0; i < 8; i++)
#pragma unroll
        for (int j = 0; j < 8; j++) acc[i][j] = 0.f;

    for (int k0 = 0; k0 < K; k0 += 8) {
        float4 av, bv;
        if (AMODE == 2) {
            int kk = k0 + aCol;
            av = (kk < HH) ? *(const float4*)(Arow0 + kk)
                           : *(const float4*)(Arow1 + kk - HH);
        } else {
            av = *(const float4*)(Arow0 + k0 + aCol);
        }
        bv = *(const float4*)(Brow + k0 + aCol);

        __syncthreads();
        As[aCol + 0][aRow] = av.x; As[aCol + 1][aRow] = av.y;
        As[aCol + 2][aRow] = av.z; As[aCol + 3][aRow] = av.w;
        Bs[aCol + 0][aRow] = bv.x; Bs[aCol + 1][aRow] = bv.y;
        Bs[aCol + 2][aRow] = bv.z; Bs[aCol + 3][aRow] = bv.w;
        __syncthreads();

#pragma unroll
        for (int kk = 0; kk < 8; kk++) {
            float a[8], b[8];
            *(float4*)&a[0] = *(const float4*)&As[kk][ty * 8];
            *(float4*)&a[4] = *(const float4*)&As[kk][ty * 8 + 4];
            *(float4*)&b[0] = *(const float4*)&Bs[kk][tx * 8];
            *(float4*)&b[4] = *(const float4*)&Bs[kk][tx * 8 + 4];
#pragma unroll
            for (int i = 0; i < 8; i++)
#pragma unroll
                for (int j = 0; j < 8; j++) acc[i][j] = fmaf(a[i], b[j], acc[i][j]);
        }
    }

#pragma unroll
    for (int i = 0; i < 8; i++) {
        size_t m = (size_t)(m0 + ty * 8 + i);
        float* crow = C + m * (size_t)N + n0 + tx * 8;
#pragma unroll
        for (int j = 0; j < 8; j++) {
            int n = n0 + tx * 8 + j;
            float v = acc[i][j] + bias[n];
            if (bias2) v += bias2[n];
            if (TANH) v = tanhf(v);
            crow[j] = v;
        }
    }
}

// ---------------- LSTM scan: persistent, 128 CTAs (co-resident), grid barrier per step -------------
__device__ __forceinline__ float sigm(float x) { return 1.f / (1.f + expf(-x)); }

__global__ void __launch_bounds__(1024, 1) lstm_scan(
    const float* __restrict__ h0, const float* __restrict__ c0,
    const float* __restrict__ Whh)
{
    extern __shared__ float s_w[];       // [4 gates][16 units][512] = 128 KB
    __shared__ float h_s[HH];
    __shared__ float c_s[16];
    __shared__ float red[16][2][4];

    const int tid  = threadIdx.x;
    const int bx   = blockIdx.x;
    const int b    = bx >> 5;            // batch
    const int j0   = (bx & 31) * 16;     // first hidden unit owned by this CTA
    const int u    = tid >> 6;           // unit within CTA (0..15)
    const int lane = tid & 63;
    const int wu   = (tid >> 5) & 1;     // warp within unit

    // stage W_hh slice (rows g*H + j0+u) into smem
    for (int idx = tid; idx < 4 * 16 * HH; idx += 1024) {
        int g  = idx >> 13;              // /8192
        int r  = idx & 8191;
        int uu = r >> 9;
        int k  = r & 511;
        s_w[idx] = Whh[((size_t)(g * HH + j0 + uu)) * HH + k];
    }
    if (tid < 16) c_s[tid] = c0[b * HH + j0 + tid];
    __syncthreads();

    const float* wi = s_w + 0 * 8192 + u * 512;
    const float* wf = s_w + 1 * 8192 + u * 512;
    const float* wg = s_w + 2 * 8192 + u * 512;
    const float* wo = s_w + 3 * 8192 + u * 512;

    for (int t = 0; t < TT; t++) {
        // prefetch this step's precomputed input gates (overlaps with dot products)
        float xgi = 0.f, xgf = 0.f, xgg = 0.f, xgo = 0.f;
        if (tid < 16) {
            const float* xp = g_xg + ((size_t)(b * TT + t)) * FH + j0 + tid;
            xgi = xp[0]; xgf = xp[HH]; xgg = xp[2 * HH]; xgo = xp[3 * HH];
        }
        if (tid < HH) {
            h_s[tid] = (t == 0) ? h0[b * HH + tid]
                                : __ldcg(&g_hbuf[(t & 1) * BB * HH + b * HH + tid]);
        }
        __syncthreads();

        float ai = 0.f, af = 0.f, ag = 0.f, ao = 0.f;
#pragma unroll
        for (int kk = 0; kk < 8; kk++) {
            int k = lane + kk * 64;
            float hv = h_s[k];
            ai = fmaf(hv, wi[k], ai);
            af = fmaf(hv, wf[k], af);
            ag = fmaf(hv, wg[k], ag);
            ao = fmaf(hv, wo[k], ao);
        }
#pragma unroll
        for (int off = 16; off > 0; off >>= 1) {
            ai += __shfl_down_sync(0xffffffffu, ai, off);
            af += __shfl_down_sync(0xffffffffu, af, off);
            ag += __shfl_down_sync(0xffffffffu, ag, off);
            ao += __shfl_down_sync(0xffffffffu, ao, off);
        }
        if ((tid & 31) == 0) {
            red[u][wu][0] = ai; red[u][wu][1] = af;
            red[u][wu][2] = ag; red[u][wu][3] = ao;
        }
        __syncthreads();

        if (tid < 16) {
            int uu = tid;
            float gi = xgi + red[uu][0][0] + red[uu][1][0];
            float gf = xgf + red[uu][0][1] + red[uu][1][1];
            float gG = xgg + red[uu][0][2] + red[uu][1][2];
            float go = xgo + red[uu][0][3] + red[uu][1][3];
            float c  = c_s[uu];
            c = sigm(gf) * c + sigm(gi) * tanhf(gG);
            float h = sigm(go) * tanhf(c);
            c_s[uu] = c;
            int j = j0 + uu;
            g_hbuf[((t + 1) & 1) * BB * HH + b * HH + j] = h;
            g_enc[((size_t)(b * TT + t)) * HH + j] = h;
            __threadfence();
        }
        __syncthreads();

        // grid barrier (all 128 CTAs co-resident: 1 CTA/SM, grid <= SM count)
        if (tid == 0) {
            unsigned my = *(volatile unsigned*)&g_bargen;
            __threadfence();
            unsigned arr = atomicAdd(&g_barcnt, 1u);
            if (arr == gridDim.x - 1) {
                g_barcnt = 0;
                __threadfence();
                atomicAdd(&g_bargen, 1u);
            } else {
                while (*(volatile unsigned*)&g_bargen == my) { }
            }
        }
        __syncthreads();
    }
}

// ---------------- s[m] = dot(tmp[m,:], wa2) + ba2 -----------------
__global__ void rowdot(const float* __restrict__ tmp, const float* __restrict__ wa2,
                       const float* __restrict__ ba2)
{
    int warp = threadIdx.x >> 5, lane = threadIdx.x & 31;
    int m = blockIdx.x * 8 + warp;
    const float* row = tmp + (size_t)m * HH;
    float acc = 0.f;
#pragma unroll
    for (int i = 0; i < 16; i++) acc = fmaf(row[lane + i * 32], wa2[lane + i * 32], acc);
#pragma unroll
    for (int off = 16; off > 0; off >>= 1) acc += __shfl_down_sync(0xffffffffu, acc, off);
    if (lane == 0) g_s[m] = acc + ba2[0];
}

// ---------------- per-batch: max, e=exp(s-max), den cumsum -> 1/den --------------
__global__ void __launch_bounds__(1024) softprep()
{
    __shared__ float p0[1024];
    __shared__ float p1[1024];
    int b = blockIdx.x, t = threadIdx.x;
    float s0 = g_s[b * TT + 2 * t], s1 = g_s[b * TT + 2 * t + 1];

    p0[t] = fmaxf(s0, s1);
    __syncthreads();
    for (int off = 512; off > 0; off >>= 1) {
        if (t < off) p0[t] = fmaxf(p0[t], p0[t + off]);
        __syncthreads();
    }
    float mx = p0[0];
    __syncthreads();

    float e0 = expf(s0 - mx), e1 = expf(s1 - mx);
    float p = e0 + e1;
    p0[t] = p;
    __syncthreads();

    float* src = p0; float* dst = p1;
    for (int off = 1; off < 1024; off <<= 1) {
        float v = src[t];
        if (t >= off) v += src[t - off];
        dst[t] = v;
        __syncthreads();
        float* tm = src; src = dst; dst = tm;
    }
    float incl = src[t];
    float excl = incl - p;
    g_e[b * TT + 2 * t]     = e0;
    g_e[b * TT + 2 * t + 1] = e1;
    g_rden[b * TT + 2 * t]     = 1.f / (excl + e0);
    g_rden[b * TT + 2 * t + 1] = 1.f / incl;
}

// ---------------- ctx[b,t,h] = cumsum_t(e*enc) / den --------------
__global__ void ctx_kernel()
{
    int id = blockIdx.x * blockDim.x + threadIdx.x;  // 0..2047
    int b = id >> 9, h = id & 511;
    const float* ep = g_e + b * TT;
    const float* rp = g_rden + b * TT;
    const float* er = g_enc + (size_t)b * TT * HH + h;
    float* cr = g_ctx + (size_t)b * TT * HH + h;
    float num = 0.f;
    for (int t = 0; t < TT; t++) {
        num = fmaf(ep[t], er[(size_t)t * HH], num);
        cr[(size_t)t * HH] = num * rp[t];
    }
}

// ---------------- launch ----------------
extern "C" void kernel_launch(void* const* d_in, const int* in_sizes, int n_in,
                              void* d_out, int out_size)
{
    const int*   input = (const int*)  d_in[0];
    const float* h0    = (const float*)d_in[1];
    const float* c0    = (const float*)d_in[2];
    const float* emb   = (const float*)d_in[3];
    const float* W_ih  = (const float*)d_in[4];
    const float* W_hh  = (const float*)d_in[5];
    const float* b_ih  = (const float*)d_in[6];
    const float* b_hh  = (const float*)d_in[7];
    const float* Wa1   = (const float*)d_in[8];
    const float* ba1   = (const float*)d_in[9];
    const float* wa2   = (const float*)d_in[10];
    const float* ba2   = (const float*)d_in[11];
    const float* Wc    = (const float*)d_in[12];
    const float* bc    = (const float*)d_in[13];
    const float* b_dec = (const float*)d_in[14];
    float* out = (float*)d_out;

    float *xg, *enc, *tmp, *ctx, *comb;
    cudaGetSymbolAddress((void**)&xg,   g_xg);
    cudaGetSymbolAddress((void**)&enc,  g_enc);
    cudaGetSymbolAddress((void**)&tmp,  g_tmp);
    cudaGetSymbolAddress((void**)&ctx,  g_ctx);
    cudaGetSymbolAddress((void**)&comb, g_comb);

    cudaFuncSetAttribute(lstm_scan, cudaFuncAttributeMaxDynamicSharedMemorySize, 4 * 16 * HH * 4);

    dim3 blk(256);

    // 1) xg = emb[input] @ W_ih^T + (b_ih + b_hh)
    gemm128<1, false><<<dim3(FH / 128, MROWS / 128), blk>>>(
        emb, nullptr, input, W_ih, b_ih, b_hh, xg, MROWS, FH, HH);

    // 2) LSTM scan -> g_enc
    lstm_scan<<<128, 1024, 4 * 16 * HH * 4>>>(h0, c0, W_hh);

    // 3) tmp = tanh(enc @ Wa1^T + ba1) ; s = tmp @ wa2 + ba2
    gemm128<0, true><<<dim3(HH / 128, MROWS / 128), blk>>>(
        enc, nullptr, nullptr, Wa1, ba1, nullptr, tmp, MROWS, HH, HH);
    rowdot<<<1024, 256>>>(tmp, wa2, ba2);

    // 4) softmax prefix pooling
    softprep<<<BB, 1024>>>();
    ctx_kernel<<<8, 256>>>();

    // 5) combined = tanh(concat(ctx, enc) @ Wc^T + bc)
    gemm128<2, true><<<dim3(HH / 128, MROWS / 128), blk>>>(
        ctx, enc, nullptr, Wc, bc, nullptr, comb, MROWS, HH, 2 * HH);

    // 6) decoded = combined @ emb^T + b_dec
    gemm128<0, false><<<dim3(VV / 128, MROWS / 128), blk>>>(
        comb, nullptr, nullptr, emb, b_dec, nullptr, out, MROWS, VV, HH);
}

// round 11
// speedup vs baseline: 1.3219x; 1.3219x over previous
#include <cuda_runtime.h>
#include <cuda_bf16.h>
#include <cstdint>
#include <math.h>

#define BB 4
#define TT 2048
#define HH 512
#define VV 32000
#define FH 2048
#define MROWS 8192

// ---------------- scratch (static device allocations; no cudaMalloc) ----------------
__device__ float g_xg[(size_t)MROWS * FH];
__device__ float g_enc[(size_t)MROWS * HH];
__device__ float g_tmp[(size_t)MROWS * HH];
__device__ float g_ctx[(size_t)MROWS * HH];
__device__ float g_comb[(size_t)MROWS * HH];
__device__ float g_hbuf[2 * BB * HH];
__device__ float g_s[MROWS];
__device__ float g_e[MROWS];
__device__ float g_rden[MROWS];
__device__ unsigned g_barcnt;
__device__ unsigned g_bargen;

__device__ __align__(16) __nv_bfloat16 g_emb_hi[(size_t)VV * HH];
__device__ __align__(16) __nv_bfloat16 g_emb_lo[(size_t)VV * HH];
__device__ __align__(16) __nv_bfloat16 g_comb_hi[(size_t)MROWS * HH];
__device__ __align__(16) __nv_bfloat16 g_comb_lo[(size_t)MROWS * HH];

// ---------------- split fp32 -> (bf16 hi, bf16 lo) ----------------
template <int SEL>
__global__ void split_bf16(const float* __restrict__ X, int n)
{
    const float* src = (SEL == 0) ? X : g_comb;
    __nv_bfloat16* Hi = (SEL == 0) ? g_emb_hi : g_comb_hi;
    __nv_bfloat16* Lo = (SEL == 0) ? g_emb_lo : g_comb_lo;
    int i = blockIdx.x * blockDim.x + threadIdx.x;
    if (i < n) {
        float x = src[i];
        __nv_bfloat16 h = __float2bfloat16(x);
        Hi[i] = h;
        Lo[i] = __float2bfloat16(x - __bfloat162float(h));
    }
}

// ---------------- HMMA decoder GEMM: out[m,n] = sum_k comb[m,k]*emb[n,k] + b_dec[n] ----
// mma.sync.m16n8k16 bf16, split-bf16 3-product scheme, fp32 register accumulators.
// CTA 256 threads = 8 warps (4 M x 2 N), CTA tile 128x128, warp tile 32x64, BK=32.

#define DS_STRIDE 40                       // bf16 elements per smem row (pad 32 -> 40)
#define DS_TILE   (128 * DS_STRIDE)        // bf16 elements per tile
#define DS_STAGE  (4 * DS_TILE)            // Ahi | Alo | Bhi | Blo

__device__ __forceinline__ void mma16816(float* c, const uint32_t* a, const uint32_t* b)
{
    asm volatile("mma.sync.aligned.m16n8k16.row.col.f32.bf16.bf16.f32 {%0,%1,%2,%3}, {%4,%5,%6,%7}, {%8,%9}, {%0,%1,%2,%3};"
        : "+f"(c[0]), "+f"(c[1]), "+f"(c[2]), "+f"(c[3])
        : "r"(a[0]), "r"(a[1]), "r"(a[2]), "r"(a[3]), "r"(b[0]), "r"(b[1]));
}

__device__ __forceinline__ void dec_ldg(uint4* rg, int tid, int m0, int n0, int kb)
{
#pragma unroll
    for (int t = 0; t < 4; t++) {
        const __nv_bfloat16* G = (t == 0) ? g_comb_hi : (t == 1) ? g_comb_lo
                               : (t == 2) ? g_emb_hi  : g_emb_lo;
        int rb = (t < 2) ? m0 : n0;
#pragma unroll
        for (int i = 0; i < 2; i++) {
            int u = tid + i * 256;          // 0..511 : 128 rows x 4 16B-units
            int row = u >> 2, cu = u & 3;
            rg[t * 2 + i] = *(const uint4*)(G + (size_t)(rb + row) * HH + kb + cu * 8);
        }
    }
}

__device__ __forceinline__ void dec_sts(const uint4* rg, int tid, __nv_bfloat16* stage)
{
#pragma unroll
    for (int t = 0; t < 4; t++) {
#pragma unroll
        for (int i = 0; i < 2; i++) {
            int u = tid + i * 256;
            int row = u >> 2, cu = u & 3;
            *(uint4*)(stage + t * DS_TILE + row * DS_STRIDE + cu * 8) = rg[t * 2 + i];
        }
    }
}

__device__ __forceinline__ void dec_compute(const __nv_bfloat16* stage, int warp_m, int warp_n,
                                            int gr, int tg, float acc[2][8][4])
{
    const __nv_bfloat16* As_h = stage;
    const __nv_bfloat16* As_l = stage + DS_TILE;
    const __nv_bfloat16* Bs_h = stage + 2 * DS_TILE;
    const __nv_bfloat16* Bs_l = stage + 3 * DS_TILE;

#pragma unroll
    for (int ks = 0; ks < 2; ks++) {
        int kb = ks * 16 + 2 * tg;
        uint32_t ah[2][4], al[2][4], bh[8][2], bl[8][2];
#pragma unroll
        for (int mf = 0; mf < 2; mf++) {
            int r0 = warp_m * 32 + mf * 16 + gr;
            const __nv_bfloat16* p = As_h + r0 * DS_STRIDE + kb;
            ah[mf][0] = *(const uint32_t*)p;
            ah[mf][1] = *(const uint32_t*)(p + 8 * DS_STRIDE);
            ah[mf][2] = *(const uint32_t*)(p + 8);
            ah[mf][3] = *(const uint32_t*)(p + 8 * DS_STRIDE + 8);
            const __nv_bfloat16* q = As_l + r0 * DS_STRIDE + kb;
            al[mf][0] = *(const uint32_t*)q;
            al[mf][1] = *(const uint32_t*)(q + 8 * DS_STRIDE);
            al[mf][2] = *(const uint32_t*)(q + 8);
            al[mf][3] = *(const uint32_t*)(q + 8 * DS_STRIDE + 8);
        }
#pragma unroll
        for (int nf = 0; nf < 8; nf++) {
            int rn = warp_n * 64 + nf * 8 + gr;
            const __nv_bfloat16* p = Bs_h + rn * DS_STRIDE + kb;
            bh[nf][0] = *(const uint32_t*)p;
            bh[nf][1] = *(const uint32_t*)(p + 8);
            const __nv_bfloat16* q = Bs_l + rn * DS_STRIDE + kb;
            bl[nf][0] = *(const uint32_t*)q;
            bl[nf][1] = *(const uint32_t*)(q + 8);
        }
#pragma unroll
        for (int mf = 0; mf < 2; mf++)
#pragma unroll
            for (int nf = 0; nf < 8; nf++) {
                mma16816(acc[mf][nf], ah[mf], bh[nf]);
                mma16816(acc[mf][nf], ah[mf], bl[nf]);
                mma16816(acc[mf][nf], al[mf], bh[nf]);
            }
    }
}

__global__ void __launch_bounds__(256, 1) dec_gemm(
    const float* __restrict__ bias, float* __restrict__ C, int N)
{
    extern __shared__ __nv_bfloat16 ds[];   // 2 stages

    const int tid = threadIdx.x;
    const int wid = tid >> 5;
    const int lane = tid & 31;
    const int gr = lane >> 2;
    const int tg = lane & 3;
    const int warp_m = wid & 3;
    const int warp_n = wid >> 2;
    const int m0 = blockIdx.y * 128;
    const int n0 = blockIdx.x * 128;

    float acc[2][8][4];
#pragma unroll
    for (int mf = 0; mf < 2; mf++)
#pragma unroll
        for (int nf = 0; nf < 8; nf++)
#pragma unroll
            for (int i = 0; i < 4; i++) acc[mf][nf][i] = 0.f;

    uint4 rg[8];
    dec_ldg(rg, tid, m0, n0, 0);
    dec_sts(rg, tid, ds);
    __syncthreads();

    for (int c = 0; c < 16; c++) {
        if (c < 15) dec_ldg(rg, tid, m0, n0, (c + 1) * 32);
        dec_compute(ds + (c & 1) * DS_STAGE, warp_m, warp_n, gr, tg, acc);
        if (c < 15) {
            dec_sts(rg, tid, ds + ((c + 1) & 1) * DS_STAGE);
            __syncthreads();
        }
    }

    float2 bv[8];
#pragma unroll
    for (int nf = 0; nf < 8; nf++) {
        int n = n0 + warp_n * 64 + nf * 8 + 2 * tg;
        bv[nf] = *(const float2*)(bias + n);
    }
#pragma unroll
    for (int mf = 0; mf < 2; mf++) {
        int m = m0 + warp_m * 32 + mf * 16 + gr;
#pragma unroll
        for (int nf = 0; nf < 8; nf++) {
            int n = n0 + warp_n * 64 + nf * 8 + 2 * tg;
            float2 v0, v1;
            v0.x = acc[mf][nf][0] + bv[nf].x;
            v0.y = acc[mf][nf][1] + bv[nf].y;
            v1.x = acc[mf][nf][2] + bv[nf].x;
            v1.y = acc[mf][nf][3] + bv[nf].y;
            *(float2*)(C + (size_t)m * N + n) = v0;
            *(float2*)(C + (size_t)(m + 8) * N + n) = v1;
        }
    }
}

// ---------------- generic 128x128x8 fp32 GEMM ----------------
template <int SRC, int DST, bool TANH>
__global__ void __launch_bounds__(256) gemm128(
    const float* __restrict__ Aext, const int* __restrict__ gidx,
    const float* __restrict__ Bw,
    const float* __restrict__ bias, const float* __restrict__ bias2,
    int M, int N, int K)
{
    __shared__ float As[8][128];
    __shared__ float Bs[8][128];

    const int tid  = threadIdx.x;
    const int m0   = blockIdx.y * 128;
    const int n0   = blockIdx.x * 128;
    const int aRow = tid >> 1;
    const int aCol = (tid & 1) << 2;
    const int tx   = tid & 15;
    const int ty   = tid >> 4;

    float* C = (DST == 0) ? g_xg : (DST == 1) ? g_tmp : g_comb;

    const float* Arow0;
    const float* Arow1 = nullptr;
    if (SRC == 0) {
        Arow0 = Aext + (size_t)gidx[m0 + aRow] * K;
    } else if (SRC == 2) {
        Arow0 = g_ctx + (size_t)(m0 + aRow) * HH;
        Arow1 = g_enc + (size_t)(m0 + aRow) * HH;
    } else {
        Arow0 = g_enc + (size_t)(m0 + aRow) * K;
    }
    const float* Brow = Bw + (size_t)(n0 + aRow) * K;

    float acc[8][8];
#pragma unroll
    for (int i = 0; i < 8; i++)
#pragma unroll
        for (int j = 0; j < 8; j++) acc[i][j] = 0.f;

    for (int k0 = 0; k0 < K; k0 += 8) {
        float4 av, bv;
        if (SRC == 2) {
            int kk = k0 + aCol;
            av = (kk < HH) ? *(const float4*)(Arow0 + kk)
                           : *(const float4*)(Arow1 + kk - HH);
        } else {
            av = *(const float4*)(Arow0 + k0 + aCol);
        }
        bv = *(const float4*)(Brow + k0 + aCol);

        __syncthreads();
        As[aCol + 0][aRow] = av.x; As[aCol + 1][aRow] = av.y;
        As[aCol + 2][aRow] = av.z; As[aCol + 3][aRow] = av.w;
        Bs[aCol + 0][aRow] = bv.x; Bs[aCol + 1][aRow] = bv.y;
        Bs[aCol + 2][aRow] = bv.z; Bs[aCol + 3][aRow] = bv.w;
        __syncthreads();

#pragma unroll
        for (int kk = 0; kk < 8; kk++) {
            float a[8], b[8];
            *(float4*)&a[0] = *(const float4*)&As[kk][ty * 8];
            *(float4*)&a[4] = *(const float4*)&As[kk][ty * 8 + 4];
            *(float4*)&b[0] = *(const float4*)&Bs[kk][tx * 8];
            *(float4*)&b[4] = *(const float4*)&Bs[kk][tx * 8 + 4];
#pragma unroll
            for (int i = 0; i < 8; i++)
#pragma unroll
                for (int j = 0; j < 8; j++) acc[i][j] = fmaf(a[i], b[j], acc[i][j]);
        }
    }

#pragma unroll
    for (int i = 0; i < 8; i++) {
        size_t m = (size_t)(m0 + ty * 8 + i);
        float* crow = C + m * (size_t)N + n0 + tx * 8;
#pragma unroll
        for (int j = 0; j < 8; j++) {
            int n = n0 + tx * 8 + j;
            float v = acc[i][j] + bias[n];
            if (bias2) v += bias2[n];
            if (TANH) v = tanhf(v);
            crow[j] = v;
        }
    }
}

// ---------------- LSTM scan ----------------
__device__ __forceinline__ float sigm(float x) { return 1.f / (1.f + expf(-x)); }

__global__ void __launch_bounds__(1024, 1) lstm_scan(
    const float* __restrict__ h0, const float* __restrict__ c0,
    const float* __restrict__ Whh)
{
    extern __shared__ float s_w[];
    __shared__ float h_s[HH];
    __shared__ float c_s[16];
    __shared__ float red[16][2][4];

    const int tid  = threadIdx.x;
    const int bx   = blockIdx.x;
    const int b    = bx >> 5;
    const int j0   = (bx & 31) * 16;
    const int u    = tid >> 6;
    const int lane = tid & 63;
    const int wu   = (tid >> 5) & 1;

    for (int idx = tid; idx < 4 * 16 * HH; idx += 1024) {
        int g  = idx >> 13;
        int r  = idx & 8191;
        int uu = r >> 9;
        int k  = r & 511;
        s_w[idx] = Whh[((size_t)(g * HH + j0 + uu)) * HH + k];
    }
    if (tid < 16) c_s[tid] = c0[b * HH + j0 + tid];
    __syncthreads();

    const float* wi = s_w + 0 * 8192 + u * 512;
    const float* wf = s_w + 1 * 8192 + u * 512;
    const float* wg = s_w + 2 * 8192 + u * 512;
    const float* wo = s_w + 3 * 8192 + u * 512;

    for (int t = 0; t < TT; t++) {
        float xgi = 0.f, xgf = 0.f, xgg = 0.f, xgo = 0.f;
        if (tid < 16) {
            const float* xp = g_xg + ((size_t)(b * TT + t)) * FH + j0 + tid;
            xgi = xp[0]; xgf = xp[HH]; xgg = xp[2 * HH]; xgo = xp[3 * HH];
        }
        if (tid < HH) {
            h_s[tid] = (t == 0) ? h0[b * HH + tid]
                                : __ldcg(&g_hbuf[(t & 1) * BB * HH + b * HH + tid]);
        }
        __syncthreads();

        float ai = 0.f, af = 0.f, ag = 0.f, ao = 0.f;
#pragma unroll
        for (int kk = 0; kk < 8; kk++) {
            int k = lane + kk * 64;
            float hv = h_s[k];
            ai = fmaf(hv, wi[k], ai);
            af = fmaf(hv, wf[k], af);
            ag = fmaf(hv, wg[k], ag);
            ao = fmaf(hv, wo[k], ao);
        }
#pragma unroll
        for (int off = 16; off > 0; off >>= 1) {
            ai += __shfl_down_sync(0xffffffffu, ai, off);
            af += __shfl_down_sync(0xffffffffu, af, off);
            ag += __shfl_down_sync(0xffffffffu, ag, off);
            ao += __shfl_down_sync(0xffffffffu, ao, off);
        }
        if ((tid & 31) == 0) {
            red[u][wu][0] = ai; red[u][wu][1] = af;
            red[u][wu][2] = ag; red[u][wu][3] = ao;
        }
        __syncthreads();

        if (tid < 16) {
            int uu = tid;
            float gi = xgi + red[uu][0][0] + red[uu][1][0];
            float gf = xgf + red[uu][0][1] + red[uu][1][1];
            float gG = xgg + red[uu][0][2] + red[uu][1][2];
            float go = xgo + red[uu][0][3] + red[uu][1][3];
            float c  = c_s[uu];
            c = sigm(gf) * c + sigm(gi) * tanhf(gG);
            float h = sigm(go) * tanhf(c);
            c_s[uu] = c;
            int j = j0 + uu;
            g_hbuf[((t + 1) & 1) * BB * HH + b * HH + j] = h;
            g_enc[((size_t)(b * TT + t)) * HH + j] = h;
            __threadfence();
        }
        __syncthreads();

        if (tid == 0) {
            unsigned my = *(volatile unsigned*)&g_bargen;
            __threadfence();
            unsigned arr = atomicAdd(&g_barcnt, 1u);
            if (arr == gridDim.x - 1) {
                g_barcnt = 0;
                __threadfence();
                atomicAdd(&g_bargen, 1u);
            } else {
                while (*(volatile unsigned*)&g_bargen == my) { }
            }
        }
        __syncthreads();
    }
}

// ---------------- s[m] = dot(g_tmp[m,:], wa2) + ba2 ----------------
__global__ void rowdot(const float* __restrict__ wa2, const float* __restrict__ ba2)
{
    int warp = threadIdx.x >> 5, lane = threadIdx.x & 31;
    int m = blockIdx.x * 8 + warp;
    const float* row = g_tmp + (size_t)m * HH;
    float acc = 0.f;
#pragma unroll
    for (int i = 0; i < 16; i++) acc = fmaf(row[lane + i * 32], wa2[lane + i * 32], acc);
#pragma unroll
    for (int off = 16; off > 0; off >>= 1) acc += __shfl_down_sync(0xffffffffu, acc, off);
    if (lane == 0) g_s[m] = acc + ba2[0];
}

// ---------------- per-batch softmax prefix prep ----------------
__global__ void __launch_bounds__(1024) softprep()
{
    __shared__ float p0[1024];
    __shared__ float p1[1024];
    int b = blockIdx.x, t = threadIdx.x;
    float s0 = g_s[b * TT + 2 * t], s1 = g_s[b * TT + 2 * t + 1];

    p0[t] = fmaxf(s0, s1);
    __syncthreads();
    for (int off = 512; off > 0; off >>= 1) {
        if (t < off) p0[t] = fmaxf(p0[t], p0[t + off]);
        __syncthreads();
    }
    float mx = p0[0];
    __syncthreads();

    float e0 = expf(s0 - mx), e1 = expf(s1 - mx);
    float p = e0 + e1;
    p0[t] = p;
    __syncthreads();

    float* src = p0; float* dst = p1;
    for (int off = 1; off < 1024; off <<= 1) {
        float v = src[t];
        if (t >= off) v += src[t - off];
        dst[t] = v;
        __syncthreads();
        float* tm = src; src = dst; dst = tm;
    }
    float incl = src[t];
    float excl = incl - p;
    g_e[b * TT + 2 * t]     = e0;
    g_e[b * TT + 2 * t + 1] = e1;
    g_rden[b * TT + 2 * t]     = 1.f / (excl + e0);
    g_rden[b * TT + 2 * t + 1] = 1.f / incl;
}

// ---------------- ctx[b,t,h] = cumsum_t(e*enc) / den ----------------
__global__ void ctx_kernel()
{
    int id = blockIdx.x * blockDim.x + threadIdx.x;
    int b = id >> 9, h = id & 511;
    const float* ep = g_e + b * TT;
    const float* rp = g_rden + b * TT;
    const float* er = g_enc + (size_t)b * TT * HH + h;
    float* cr = g_ctx + (size_t)b * TT * HH + h;
    float num = 0.f;
    for (int t = 0; t < TT; t++) {
        num = fmaf(ep[t], er[(size_t)t * HH], num);
        cr[(size_t)t * HH] = num * rp[t];
    }
}

// ---------------- launch ----------------
extern "C" void kernel_launch(void* const* d_in, const int* in_sizes, int n_in,
                              void* d_out, int out_size)
{
    const int*   input = (const int*)  d_in[0];
    const float* h0    = (const float*)d_in[1];
    const float* c0    = (const float*)d_in[2];
    const float* emb   = (const float*)d_in[3];
    const float* W_ih  = (const float*)d_in[4];
    const float* W_hh  = (const float*)d_in[5];
    const float* b_ih  = (const float*)d_in[6];
    const float* b_hh  = (const float*)d_in[7];
    const float* Wa1   = (const float*)d_in[8];
    const float* ba1   = (const float*)d_in[9];
    const float* wa2   = (const float*)d_in[10];
    const float* ba2   = (const float*)d_in[11];
    const float* Wc    = (const float*)d_in[12];
    const float* bc    = (const float*)d_in[13];
    const float* b_dec = (const float*)d_in[14];
    float* out = (float*)d_out;

    cudaFuncSetAttribute(lstm_scan, cudaFuncAttributeMaxDynamicSharedMemorySize, 4 * 16 * HH * 4);
    cudaFuncSetAttribute(dec_gemm, cudaFuncAttributeMaxDynamicSharedMemorySize,
                         2 * DS_STAGE * (int)sizeof(__nv_bfloat16));

    dim3 blk(256);

    split_bf16<0><<<(VV * HH + 255) / 256, 256>>>(emb, VV * HH);

    gemm128<0, 0, false><<<dim3(FH / 128, MROWS / 128), blk>>>(
        emb, input, W_ih, b_ih, b_hh, MROWS, FH, HH);

    lstm_scan<<<128, 1024, 4 * 16 * HH * 4>>>(h0, c0, W_hh);

    gemm128<1, 1, true><<<dim3(HH / 128, MROWS / 128), blk>>>(
        nullptr, nullptr, Wa1, ba1, nullptr, MROWS, HH, HH);
    rowdot<<<1024, 256>>>(wa2, ba2);

    softprep<<<BB, 1024>>>();
    ctx_kernel<<<8, 256>>>();

    gemm128<2, 2, true><<<dim3(HH / 128, MROWS / 128), blk>>>(
        nullptr, nullptr, Wc, bc, nullptr, MROWS, HH, 2 * HH);

    split_bf16<1><<<(MROWS * HH + 255) / 256, 256>>>(nullptr, MROWS * HH);

    dec_gemm<<<dim3(VV / 128, MROWS / 128), blk,
               2 * DS_STAGE * (int)sizeof(__nv_bfloat16)>>>(b_dec, out, VV);
}

// round 12
// speedup vs baseline: 1.4430x; 1.0916x over previous
#include <cuda_runtime.h>
#include <cuda_bf16.h>
#include <cstdint>
#include <math.h>

#define BB 4
#define TT 2048
#define HH 512
#define VV 32000
#define FH 2048
#define MROWS 8192

// ---------------- scratch (static device allocations; no cudaMalloc) ----------------
__device__ float g_xg[(size_t)MROWS * FH];
__device__ float g_enc[(size_t)MROWS * HH];
__device__ float g_tmp[(size_t)MROWS * HH];
__device__ float g_ctx[(size_t)MROWS * HH];
__device__ float g_comb[(size_t)MROWS * HH];
__device__ float g_hbuf[2 * BB * HH];
__device__ float g_s[MROWS];
__device__ float g_e[MROWS];
__device__ float g_rden[MROWS];
__device__ float g_part[BB * 32 * HH];
__device__ unsigned g_barcnt;
__device__ unsigned g_bargen;

__device__ __align__(16) __nv_bfloat16 g_emb_hi[(size_t)VV * HH];
__device__ __align__(16) __nv_bfloat16 g_emb_lo[(size_t)VV * HH];
__device__ __align__(16) __nv_bfloat16 g_comb_hi[(size_t)MROWS * HH];
__device__ __align__(16) __nv_bfloat16 g_comb_lo[(size_t)MROWS * HH];

// ---------------- helpers ----------------
__device__ __forceinline__ uint32_t s2u(const void* p) {
    uint32_t a;
    asm("{ .reg .u64 t; cvta.to.shared.u64 t, %1; cvt.u32.u64 %0, t; }" : "=r"(a) : "l"(p));
    return a;
}
__device__ __forceinline__ void mma16816(float* c, const uint32_t* a, const uint32_t* b)
{
    asm volatile("mma.sync.aligned.m16n8k16.row.col.f32.bf16.bf16.f32 {%0,%1,%2,%3}, {%4,%5,%6,%7}, {%8,%9}, {%0,%1,%2,%3};"
        : "+f"(c[0]), "+f"(c[1]), "+f"(c[2]), "+f"(c[3])
        : "r"(a[0]), "r"(a[1]), "r"(a[2]), "r"(a[3]), "r"(b[0]), "r"(b[1]));
}
__device__ __forceinline__ void ldmx4(uint32_t* r, uint32_t a) {
    asm volatile("ldmatrix.sync.aligned.m8n8.x4.shared.b16 {%0,%1,%2,%3}, [%4];"
        : "=r"(r[0]), "=r"(r[1]), "=r"(r[2]), "=r"(r[3]) : "r"(a));
}

// ---------------- split fp32 -> (bf16 hi, bf16 lo) ----------------
template <int SEL>
__global__ void split_bf16(const float* __restrict__ X, int n)
{
    const float* src = (SEL == 0) ? X : g_comb;
    __nv_bfloat16* Hi = (SEL == 0) ? g_emb_hi : g_comb_hi;
    __nv_bfloat16* Lo = (SEL == 0) ? g_emb_lo : g_comb_lo;
    int i = blockIdx.x * blockDim.x + threadIdx.x;
    if (i < n) {
        float x = src[i];
        __nv_bfloat16 h = __float2bfloat16(x);
        Hi[i] = h;
        Lo[i] = __float2bfloat16(x - __bfloat162float(h));
    }
}

// ---------------- HMMA decoder: out[m,n] = sum_k comb[m,k]*emb[n,k] + b_dec[n] ----
// split-bf16 (Ahi*Bhi + Ahi*Blo + Alo*Bhi), cp.async 2-stage pipeline, ldmatrix fragments.
// CTA 256 thr = 8 warps (4 M x 2 N), tile 128x128, warp tile 32x64, BK=32.

#define DS_STRIDE 40                         // bf16 elems per smem row (pad 32->40, rows 80B)
#define DS_TILE   (128 * DS_STRIDE)          // elems per tile
#define DS_TILE_B (DS_TILE * 2)
#define DS_STAGE_B (4 * DS_TILE_B)           // 40960 B: Ahi|Alo|Bhi|Blo

__device__ __forceinline__ void dec_prefetch(uint32_t sbase, int buf, int tid, int m0, int n0, int kb)
{
    uint32_t dstb = sbase + (uint32_t)buf * DS_STAGE_B;
#pragma unroll
    for (int t = 0; t < 4; t++) {
        const __nv_bfloat16* G = (t == 0) ? g_comb_hi : (t == 1) ? g_comb_lo
                               : (t == 2) ? g_emb_hi  : g_emb_lo;
        int rb = (t < 2) ? m0 : n0;
#pragma unroll
        for (int i = 0; i < 2; i++) {
            int u = tid + i * 256;
            int row = u >> 2, cu = u & 3;
            const void* src = (const void*)(G + (size_t)(rb + row) * HH + kb + cu * 8);
            uint32_t dst = dstb + (uint32_t)(t * DS_TILE_B) + (uint32_t)((row * DS_STRIDE + cu * 8) * 2);
            asm volatile("cp.async.cg.shared.global [%0], [%1], 16;" :: "r"(dst), "l"(src));
        }
    }
    asm volatile("cp.async.commit_group;" ::: "memory");
}

__device__ __forceinline__ void dec_compute_stage(uint32_t sb, int warp_m, int warp_n,
                                                  int lane, float acc[2][8][4])
{
    const int arow = warp_m * 32 + 8 * ((lane >> 3) & 1) + (lane & 7);
    const int brow = warp_n * 64 + 8 * (lane >> 4) + (lane & 7);
#pragma unroll
    for (int ks = 0; ks < 2; ks++) {
        const int acol = ks * 16 + 8 * (lane >> 4);
        const int bcol = ks * 16 + 8 * ((lane >> 3) & 1);
        uint32_t ah[2][4], al[2][4];
#pragma unroll
        for (int mf = 0; mf < 2; mf++) {
            uint32_t ra = sb + (uint32_t)(((arow + mf * 16) * DS_STRIDE + acol) * 2);
            ldmx4(ah[mf], ra);
            ldmx4(al[mf], ra + DS_TILE_B);
        }
#pragma unroll
        for (int nfp = 0; nfp < 4; nfp++) {
            uint32_t rb = sb + (uint32_t)(2 * DS_TILE_B)
                        + (uint32_t)(((brow + nfp * 16) * DS_STRIDE + bcol) * 2);
            uint32_t bh[4], bl[4];
            ldmx4(bh, rb);
            ldmx4(bl, rb + DS_TILE_B);
#pragma unroll
            for (int mf = 0; mf < 2; mf++) {
                mma16816(acc[mf][2 * nfp + 0], ah[mf], bh + 0);
                mma16816(acc[mf][2 * nfp + 0], ah[mf], bl + 0);
                mma16816(acc[mf][2 * nfp + 0], al[mf], bh + 0);
                mma16816(acc[mf][2 * nfp + 1], ah[mf], bh + 2);
                mma16816(acc[mf][2 * nfp + 1], ah[mf], bl + 2);
                mma16816(acc[mf][2 * nfp + 1], al[mf], bh + 2);
            }
        }
    }
}

__global__ void __launch_bounds__(256, 2) dec_gemm(
    const float* __restrict__ bias, float* __restrict__ C, int N)
{
    extern __shared__ __nv_bfloat16 ds[];

    const int tid = threadIdx.x;
    const int wid = tid >> 5;
    const int lane = tid & 31;
    const int gr = lane >> 2;
    const int tg = lane & 3;
    const int warp_m = wid & 3;
    const int warp_n = wid >> 2;
    const int m0 = blockIdx.y * 128;
    const int n0 = blockIdx.x * 128;
    const uint32_t sbase = s2u(ds);

    float acc[2][8][4];
#pragma unroll
    for (int mf = 0; mf < 2; mf++)
#pragma unroll
        for (int nf = 0; nf < 8; nf++)
#pragma unroll
            for (int i = 0; i < 4; i++) acc[mf][nf][i] = 0.f;

    dec_prefetch(sbase, 0, tid, m0, n0, 0);

    for (int c = 0; c < 16; c++) {
        if (c + 1 < 16) {
            dec_prefetch(sbase, (c + 1) & 1, tid, m0, n0, (c + 1) * 32);
            asm volatile("cp.async.wait_group 1;" ::: "memory");
        } else {
            asm volatile("cp.async.wait_group 0;" ::: "memory");
        }
        __syncthreads();
        dec_compute_stage(sbase + (uint32_t)(c & 1) * DS_STAGE_B, warp_m, warp_n, lane, acc);
        __syncthreads();
    }

    float2 bv[8];
#pragma unroll
    for (int nf = 0; nf < 8; nf++) {
        int n = n0 + warp_n * 64 + nf * 8 + 2 * tg;
        bv[nf] = *(const float2*)(bias + n);
    }
#pragma unroll
    for (int mf = 0; mf < 2; mf++) {
        int m = m0 + warp_m * 32 + mf * 16 + gr;
#pragma unroll
        for (int nf = 0; nf < 8; nf++) {
            int n = n0 + warp_n * 64 + nf * 8 + 2 * tg;
            float2 v0, v1;
            v0.x = acc[mf][nf][0] + bv[nf].x;
            v0.y = acc[mf][nf][1] + bv[nf].y;
            v1.x = acc[mf][nf][2] + bv[nf].x;
            v1.y = acc[mf][nf][3] + bv[nf].y;
            *(float2*)(C + (size_t)m * N + n) = v0;
            *(float2*)(C + (size_t)(m + 8) * N + n) = v1;
        }
    }
}

// ---------------- generic 128x128x8 fp32 GEMM ----------------
template <int SRC, int DST, bool TANH>
__global__ void __launch_bounds__(256) gemm128(
    const float* __restrict__ Aext, const int* __restrict__ gidx,
    const float* __restrict__ Bw,
    const float* __restrict__ bias, const float* __restrict__ bias2,
    int M, int N, int K)
{
    __shared__ float As[8][128];
    __shared__ float Bs[8][128];

    const int tid  = threadIdx.x;
    const int m0   = blockIdx.y * 128;
    const int n0   = blockIdx.x * 128;
    const int aRow = tid >> 1;
    const int aCol = (tid & 1) << 2;
    const int tx   = tid & 15;
    const int ty   = tid >> 4;

    float* C = (DST == 0) ? g_xg : (DST == 1) ? g_tmp : g_comb;

    const float* Arow0;
    const float* Arow1 = nullptr;
    if (SRC == 0) {
        Arow0 = Aext + (size_t)gidx[m0 + aRow] * K;
    } else if (SRC == 2) {
        Arow0 = g_ctx + (size_t)(m0 + aRow) * HH;
        Arow1 = g_enc + (size_t)(m0 + aRow) * HH;
    } else {
        Arow0 = g_enc + (size_t)(m0 + aRow) * K;
    }
    const float* Brow = Bw + (size_t)(n0 + aRow) * K;

    float acc[8][8];
#pragma unroll
    for (int i = 0; i < 8; i++)
#pragma unroll
        for (int j = 0; j < 8; j++) acc[i][j] = 0.f;

    for (int k0 = 0; k0 < K; k0 += 8) {
        float4 av, bv;
        if (SRC == 2) {
            int kk = k0 + aCol;
            av = (kk < HH) ? *(const float4*)(Arow0 + kk)
                           : *(const float4*)(Arow1 + kk - HH);
        } else {
            av = *(const float4*)(Arow0 + k0 + aCol);
        }
        bv = *(const float4*)(Brow + k0 + aCol);

        __syncthreads();
        As[aCol + 0][aRow] = av.x; As[aCol + 1][aRow] = av.y;
        As[aCol + 2][aRow] = av.z; As[aCol + 3][aRow] = av.w;
        Bs[aCol + 0][aRow] = bv.x; Bs[aCol + 1][aRow] = bv.y;
        Bs[aCol + 2][aRow] = bv.z; Bs[aCol + 3][aRow] = bv.w;
        __syncthreads();

#pragma unroll
        for (int kk = 0; kk < 8; kk++) {
            float a[8], b[8];
            *(float4*)&a[0] = *(const float4*)&As[kk][ty * 8];
            *(float4*)&a[4] = *(const float4*)&As[kk][ty * 8 + 4];
            *(float4*)&b[0] = *(const float4*)&Bs[kk][tx * 8];
            *(float4*)&b[4] = *(const float4*)&Bs[kk][tx * 8 + 4];
#pragma unroll
            for (int i = 0; i < 8; i++)
#pragma unroll
                for (int j = 0; j < 8; j++) acc[i][j] = fmaf(a[i], b[j], acc[i][j]);
        }
    }

#pragma unroll
    for (int i = 0; i < 8; i++) {
        size_t m = (size_t)(m0 + ty * 8 + i);
        float* crow = C + m * (size_t)N + n0 + tx * 8;
#pragma unroll
        for (int j = 0; j < 8; j++) {
            int n = n0 + tx * 8 + j;
            float v = acc[i][j] + bias[n];
            if (bias2) v += bias2[n];
            if (TANH) v = tanhf(v);
            crow[j] = v;
        }
    }
}

// ---------------- LSTM scan ----------------
__device__ __forceinline__ float sigm(float x) { return 1.f / (1.f + expf(-x)); }

__global__ void __launch_bounds__(1024, 1) lstm_scan(
    const float* __restrict__ h0, const float* __restrict__ c0,
    const float* __restrict__ Whh)
{
    extern __shared__ float s_w[];
    __shared__ float h_s[HH];
    __shared__ float c_s[16];
    __shared__ float red[16][2][4];

    const int tid  = threadIdx.x;
    const int bx   = blockIdx.x;
    const int b    = bx >> 5;
    const int j0   = (bx & 31) * 16;
    const int u    = tid >> 6;
    const int lane = tid & 63;
    const int wu   = (tid >> 5) & 1;

    for (int idx = tid; idx < 4 * 16 * HH; idx += 1024) {
        int g  = idx >> 13;
        int r  = idx & 8191;
        int uu = r >> 9;
        int k  = r & 511;
        s_w[idx] = Whh[((size_t)(g * HH + j0 + uu)) * HH + k];
    }
    if (tid < 16) c_s[tid] = c0[b * HH + j0 + tid];
    __syncthreads();

    const float* wi = s_w + 0 * 8192 + u * 512;
    const float* wf = s_w + 1 * 8192 + u * 512;
    const float* wg = s_w + 2 * 8192 + u * 512;
    const float* wo = s_w + 3 * 8192 + u * 512;

    for (int t = 0; t < TT; t++) {
        float xgi = 0.f, xgf = 0.f, xgg = 0.f, xgo = 0.f;
        if (tid < 16) {
            const float* xp = g_xg + ((size_t)(b * TT + t)) * FH + j0 + tid;
            xgi = xp[0]; xgf = xp[HH]; xgg = xp[2 * HH]; xgo = xp[3 * HH];
        }
        if (tid < HH) {
            h_s[tid] = (t == 0) ? h0[b * HH + tid]
                                : __ldcg(&g_hbuf[(t & 1) * BB * HH + b * HH + tid]);
        }
        __syncthreads();

        float ai = 0.f, af = 0.f, ag = 0.f, ao = 0.f;
#pragma unroll
        for (int kk = 0; kk < 8; kk++) {
            int k = lane + kk * 64;
            float hv = h_s[k];
            ai = fmaf(hv, wi[k], ai);
            af = fmaf(hv, wf[k], af);
            ag = fmaf(hv, wg[k], ag);
            ao = fmaf(hv, wo[k], ao);
        }
#pragma unroll
        for (int off = 16; off > 0; off >>= 1) {
            ai += __shfl_down_sync(0xffffffffu, ai, off);
            af += __shfl_down_sync(0xffffffffu, af, off);
            ag += __shfl_down_sync(0xffffffffu, ag, off);
            ao += __shfl_down_sync(0xffffffffu, ao, off);
        }
        if ((tid & 31) == 0) {
            red[u][wu][0] = ai; red[u][wu][1] = af;
            red[u][wu][2] = ag; red[u][wu][3] = ao;
        }
        __syncthreads();

        if (tid < 16) {
            int uu = tid;
            float gi = xgi + red[uu][0][0] + red[uu][1][0];
            float gf = xgf + red[uu][0][1] + red[uu][1][1];
            float gG = xgg + red[uu][0][2] + red[uu][1][2];
            float go = xgo + red[uu][0][3] + red[uu][1][3];
            float c  = c_s[uu];
            c = sigm(gf) * c + sigm(gi) * tanhf(gG);
            float h = sigm(go) * tanhf(c);
            c_s[uu] = c;
            int j = j0 + uu;
            g_hbuf[((t + 1) & 1) * BB * HH + b * HH + j] = h;
            g_enc[((size_t)(b * TT + t)) * HH + j] = h;
            __threadfence();
        }
        __syncthreads();

        if (tid == 0) {
            unsigned my = *(volatile unsigned*)&g_bargen;
            __threadfence();
            unsigned arr = atomicAdd(&g_barcnt, 1u);
            if (arr == gridDim.x - 1) {
                g_barcnt = 0;
                __threadfence();
                atomicAdd(&g_bargen, 1u);
            } else {
                while (*(volatile unsigned*)&g_bargen == my) { }
            }
        }
        __syncthreads();
    }
}

// ---------------- s[m] = dot(g_tmp[m,:], wa2) + ba2 ----------------
__global__ void rowdot(const float* __restrict__ wa2, const float* __restrict__ ba2)
{
    int warp = threadIdx.x >> 5, lane = threadIdx.x & 31;
    int m = blockIdx.x * 8 + warp;
    const float* row = g_tmp + (size_t)m * HH;
    float acc = 0.f;
#pragma unroll
    for (int i = 0; i < 16; i++) acc = fmaf(row[lane + i * 32], wa2[lane + i * 32], acc);
#pragma unroll
    for (int off = 16; off > 0; off >>= 1) acc += __shfl_down_sync(0xffffffffu, acc, off);
    if (lane == 0) g_s[m] = acc + ba2[0];
}

// ---------------- per-batch softmax prefix prep ----------------
__global__ void __launch_bounds__(1024) softprep()
{
    __shared__ float p0[1024];
    __shared__ float p1[1024];
    int b = blockIdx.x, t = threadIdx.x;
    float s0 = g_s[b * TT + 2 * t], s1 = g_s[b * TT + 2 * t + 1];

    p0[t] = fmaxf(s0, s1);
    __syncthreads();
    for (int off = 512; off > 0; off >>= 1) {
        if (t < off) p0[t] = fmaxf(p0[t], p0[t + off]);
        __syncthreads();
    }
    float mx = p0[0];
    __syncthreads();

    float e0 = expf(s0 - mx), e1 = expf(s1 - mx);
    float p = e0 + e1;
    p0[t] = p;
    __syncthreads();

    float* src = p0; float* dst = p1;
    for (int off = 1; off < 1024; off <<= 1) {
        float v = src[t];
        if (t >= off) v += src[t - off];
        dst[t] = v;
        __syncthreads();
        float* tm = src; src = dst; dst = tm;
    }
    float incl = src[t];
    float excl = incl - p;
    g_e[b * TT + 2 * t]     = e0;
    g_e[b * TT + 2 * t + 1] = e1;
    g_rden[b * TT + 2 * t]     = 1.f / (excl + e0);
    g_rden[b * TT + 2 * t + 1] = 1.f / incl;
}

// ---------------- ctx two-phase chunked scan ----------------
// phase 1: per-(b, chunk, h) partial sum over 64 timesteps
__global__ void ctx_part()
{
    int id = blockIdx.x * blockDim.x + threadIdx.x;   // 65536
    int b = id >> 14;
    int c = (id >> 9) & 31;
    int h = id & 511;
    const float* ep = g_e + b * TT + c * 64;
    const float* er = g_enc + (size_t)b * TT * HH + (size_t)(c * 64) * HH + h;
    float s = 0.f;
#pragma unroll 4
    for (int t = 0; t < 64; t++) s = fmaf(ep[t], er[(size_t)t * HH], s);
    g_part[(b * 32 + c) * HH + h] = s;
}
// phase 2: exclusive prefix over chunks + local scan + divide
__global__ void ctx_main()
{
    int id = blockIdx.x * blockDim.x + threadIdx.x;
    int b = id >> 14;
    int c = (id >> 9) & 31;
    int h = id & 511;
    float base = 0.f;
    for (int cc = 0; cc < c; cc++) base += g_part[(b * 32 + cc) * HH + h];
    const float* ep = g_e + b * TT + c * 64;
    const float* rp = g_rden + b * TT + c * 64;
    const float* er = g_enc + (size_t)b * TT * HH + (size_t)(c * 64) * HH + h;
    float* cr = g_ctx + (size_t)b * TT * HH + (size_t)(c * 64) * HH + h;
    float num = base;
    for (int t = 0; t < 64; t++) {
        num = fmaf(ep[t], er[(size_t)t * HH], num);
        cr[(size_t)t * HH] = num * rp[t];
    }
}

// ---------------- launch ----------------
extern "C" void kernel_launch(void* const* d_in, const int* in_sizes, int n_in,
                              void* d_out, int out_size)
{
    const int*   input = (const int*)  d_in[0];
    const float* h0    = (const float*)d_in[1];
    const float* c0    = (const float*)d_in[2];
    const float* emb   = (const float*)d_in[3];
    const float* W_ih  = (const float*)d_in[4];
    const float* W_hh  = (const float*)d_in[5];
    const float* b_ih  = (const float*)d_in[6];
    const float* b_hh  = (const float*)d_in[7];
    const float* Wa1   = (const float*)d_in[8];
    const float* ba1   = (const float*)d_in[9];
    const float* wa2   = (const float*)d_in[10];
    const float* ba2   = (const float*)d_in[11];
    const float* Wc    = (const float*)d_in[12];
    const float* bc    = (const float*)d_in[13];
    const float* b_dec = (const float*)d_in[14];
    float* out = (float*)d_out;

    cudaFuncSetAttribute(lstm_scan, cudaFuncAttributeMaxDynamicSharedMemorySize, 4 * 16 * HH * 4);
    cudaFuncSetAttribute(dec_gemm, cudaFuncAttributeMaxDynamicSharedMemorySize, 2 * DS_STAGE_B);

    dim3 blk(256);

    split_bf16<0><<<(VV * HH + 255) / 256, 256>>>(emb, VV * HH);

    gemm128<0, 0, false><<<dim3(FH / 128, MROWS / 128), blk>>>(
        emb, input, W_ih, b_ih, b_hh, MROWS, FH, HH);

    lstm_scan<<<128, 1024, 4 * 16 * HH * 4>>>(h0, c0, W_hh);

    gemm128<1, 1, true><<<dim3(HH / 128, MROWS / 128), blk>>>(
        nullptr, nullptr, Wa1, ba1, nullptr, MROWS, HH, HH);
    rowdot<<<1024, 256>>>(wa2, ba2);

    softprep<<<BB, 1024>>>();
    ctx_part<<<256, 256>>>();
    ctx_main<<<256, 256>>>();

    gemm128<2, 2, true><<<dim3(HH / 128, MROWS / 128), blk>>>(
        nullptr, nullptr, Wc, bc, nullptr, MROWS, HH, 2 * HH);

    split_bf16<1><<<(MROWS * HH + 255) / 256, 256>>>(nullptr, MROWS * HH);

    dec_gemm<<<dim3(VV / 128, MROWS / 128), blk, 2 * DS_STAGE_B>>>(b_dec, out, VV);
}

// round 14
// speedup vs baseline: 2.0119x; 1.3942x over previous
#include <cuda_runtime.h>
#include <cuda_fp16.h>
#include <cstdint>
#include <math.h>

#define BB 4
#define TT 2048
#define HH 512
#define VV 32000
#define FH 2048
#define MROWS 8192

// ---------------- scratch (static device allocations; no cudaMalloc) ----------------
__device__ float g_xg[(size_t)MROWS * FH];
__device__ float g_enc[(size_t)MROWS * HH];
__device__ float g_tmp[(size_t)MROWS * HH];
__device__ float g_ctx[(size_t)MROWS * HH];
__device__ float g_comb[(size_t)MROWS * HH];
__device__ float g_hbuf[2 * BB * HH];
__device__ float g_s[MROWS];
__device__ float g_e[MROWS];
__device__ float g_rden[MROWS];
__device__ float g_part[BB * 32 * HH];
__device__ unsigned g_barcnt;
__device__ unsigned g_bargen;

__device__ __align__(16) __half g_emb_h[(size_t)VV * HH];
__device__ __align__(16) __half g_comb_h[(size_t)MROWS * HH];

// ---------------- helpers ----------------
__device__ __forceinline__ uint32_t s2u(const void* p) {
    uint32_t a;
    asm("{ .reg .u64 t; cvta.to.shared.u64 t, %1; cvt.u32.u64 %0, t; }" : "=r"(a) : "l"(p));
    return a;
}
__device__ __forceinline__ void mma16816h(float* c, const uint32_t* a, const uint32_t* b)
{
    asm volatile("mma.sync.aligned.m16n8k16.row.col.f32.f16.f16.f32 {%0,%1,%2,%3}, {%4,%5,%6,%7}, {%8,%9}, {%0,%1,%2,%3};"
        : "+f"(c[0]), "+f"(c[1]), "+f"(c[2]), "+f"(c[3])
        : "r"(a[0]), "r"(a[1]), "r"(a[2]), "r"(a[3]), "r"(b[0]), "r"(b[1]));
}
__device__ __forceinline__ void ldmx4(uint32_t* r, uint32_t a) {
    asm volatile("ldmatrix.sync.aligned.m8n8.x4.shared.b16 {%0,%1,%2,%3}, [%4];"
        : "=r"(r[0]), "=r"(r[1]), "=r"(r[2]), "=r"(r[3]) : "r"(a));
}

// ---------------- convert fp32 -> fp16 ----------------
template <int SEL>
__global__ void to_half(const float* __restrict__ X, int n)
{
    const float* src = (SEL == 0) ? X : g_comb;
    __half* dst = (SEL == 0) ? g_emb_h : g_comb_h;
    int i = blockIdx.x * blockDim.x + threadIdx.x;
    if (i < n) dst[i] = __float2half_rn(src[i]);
}

// ---------------- HMMA decoder: out[m,n] = sum_k comb[m,k]*emb[n,k] + b_dec[n] ----
// single-product fp16, fp32 accum. cp.async 2-stage, ldmatrix.
// CTA 256 thr = 8 warps (4 M x 2 N), tile 128x128, warp tile 32x64, BK=32.

#define DS_STRIDE 40                         // fp16 elems per smem row (pad 32->40, 80B rows)
#define DS_TILE   (128 * DS_STRIDE)
#define DS_TILE_B (DS_TILE * 2)              // 10240 B
#define DS_STAGE_B (2 * DS_TILE_B)           // 20480 B : A | B

__device__ __forceinline__ void dec_prefetch(uint32_t sbase, int buf, int tid, int m0, int n0, int kb)
{
    uint32_t dstb = sbase + (uint32_t)buf * DS_STAGE_B;
#pragma unroll
    for (int t = 0; t < 2; t++) {
        const __half* G = (t == 0) ? g_comb_h : g_emb_h;
        int rb = (t == 0) ? m0 : n0;
#pragma unroll
        for (int i = 0; i < 2; i++) {
            int u = tid + i * 256;
            int row = u >> 2, cu = u & 3;
            const void* src = (const void*)(G + (size_t)(rb + row) * HH + kb + cu * 8);
            uint32_t dst = dstb + (uint32_t)(t * DS_TILE_B) + (uint32_t)((row * DS_STRIDE + cu * 8) * 2);
            asm volatile("cp.async.cg.shared.global [%0], [%1], 16;" :: "r"(dst), "l"(src));
        }
    }
    asm volatile("cp.async.commit_group;" ::: "memory");
}

__device__ __forceinline__ void dec_compute_stage(uint32_t sb, int warp_m, int warp_n,
                                                  int lane, float acc[2][8][4])
{
    const int arow = warp_m * 32 + 8 * ((lane >> 3) & 1) + (lane & 7);
    const int brow = warp_n * 64 + 8 * (lane >> 4) + (lane & 7);
#pragma unroll
    for (int ks = 0; ks < 2; ks++) {
        const int acol = ks * 16 + 8 * (lane >> 4);
        const int bcol = ks * 16 + 8 * ((lane >> 3) & 1);
        uint32_t ah[2][4];
#pragma unroll
        for (int mf = 0; mf < 2; mf++) {
            uint32_t ra = sb + (uint32_t)(((arow + mf * 16) * DS_STRIDE + acol) * 2);
            ldmx4(ah[mf], ra);
        }
#pragma unroll
        for (int nfp = 0; nfp < 4; nfp++) {
            uint32_t rb = sb + (uint32_t)DS_TILE_B
                        + (uint32_t)(((brow + nfp * 16) * DS_STRIDE + bcol) * 2);
            uint32_t bh[4];
            ldmx4(bh, rb);
#pragma unroll
            for (int mf = 0; mf < 2; mf++) {
                mma16816h(acc[mf][2 * nfp + 0], ah[mf], bh + 0);
                mma16816h(acc[mf][2 * nfp + 1], ah[mf], bh + 2);
            }
        }
    }
}

__global__ void __launch_bounds__(256, 2) dec_gemm(
    const float* __restrict__ bias, float* __restrict__ C, int N)
{
    extern __shared__ __half ds[];

    const int tid = threadIdx.x;
    const int wid = tid >> 5;
    const int lane = tid & 31;
    const int gr = lane >> 2;
    const int tg = lane & 3;
    const int warp_m = wid & 3;
    const int warp_n = wid >> 2;
    const int m0 = blockIdx.y * 128;
    const int n0 = blockIdx.x * 128;
    const uint32_t sbase = s2u(ds);

    float acc[2][8][4];
#pragma unroll
    for (int mf = 0; mf < 2; mf++)
#pragma unroll
        for (int nf = 0; nf < 8; nf++)
#pragma unroll
            for (int i = 0; i < 4; i++) acc[mf][nf][i] = 0.f;

    dec_prefetch(sbase, 0, tid, m0, n0, 0);

    for (int c = 0; c < 16; c++) {
        if (c + 1 < 16) {
            dec_prefetch(sbase, (c + 1) & 1, tid, m0, n0, (c + 1) * 32);
            asm volatile("cp.async.wait_group 1;" ::: "memory");
        } else {
            asm volatile("cp.async.wait_group 0;" ::: "memory");
        }
        __syncthreads();
        dec_compute_stage(sbase + (uint32_t)(c & 1) * DS_STAGE_B, warp_m, warp_n, lane, acc);
        __syncthreads();
    }

    float2 bv[8];
#pragma unroll
    for (int nf = 0; nf < 8; nf++) {
        int n = n0 + warp_n * 64 + nf * 8 + 2 * tg;
        bv[nf] = *(const float2*)(bias + n);
    }
#pragma unroll
    for (int mf = 0; mf < 2; mf++) {
        int m = m0 + warp_m * 32 + mf * 16 + gr;
#pragma unroll
        for (int nf = 0; nf < 8; nf++) {
            int n = n0 + warp_n * 64 + nf * 8 + 2 * tg;
            float2 v0, v1;
            v0.x = acc[mf][nf][0] + bv[nf].x;
            v0.y = acc[mf][nf][1] + bv[nf].y;
            v1.x = acc[mf][nf][2] + bv[nf].x;
            v1.y = acc[mf][nf][3] + bv[nf].y;
            *(float2*)(C + (size_t)m * N + n) = v0;
            *(float2*)(C + (size_t)(m + 8) * N + n) = v1;
        }
    }
}

// ---------------- generic 128x128x8 fp32 GEMM ----------------
template <int SRC, int DST, bool TANH>
__global__ void __launch_bounds__(256) gemm128(
    const float* __restrict__ Aext, const int* __restrict__ gidx,
    const float* __restrict__ Bw,
    const float* __restrict__ bias, const float* __restrict__ bias2,
    int M, int N, int K)
{
    __shared__ float As[8][128];
    __shared__ float Bs[8][128];

    const int tid  = threadIdx.x;
    const int m0   = blockIdx.y * 128;
    const int n0   = blockIdx.x * 128;
    const int aRow = tid >> 1;
    const int aCol = (tid & 1) << 2;
    const int tx   = tid & 15;
    const int ty   = tid >> 4;

    float* C = (DST == 0) ? g_xg : (DST == 1) ? g_tmp : g_comb;

    const float* Arow0;
    const float* Arow1 = nullptr;
    if (SRC == 0) {
        Arow0 = Aext + (size_t)gidx[m0 + aRow] * K;
    } else if (SRC == 2) {
        Arow0 = g_ctx + (size_t)(m0 + aRow) * HH;
        Arow1 = g_enc + (size_t)(m0 + aRow) * HH;
    } else {
        Arow0 = g_enc + (size_t)(m0 + aRow) * K;
    }
    const float* Brow = Bw + (size_t)(n0 + aRow) * K;

    float acc[8][8];
#pragma unroll
    for (int i = 0; i < 8; i++)
#pragma unroll
        for (int j = 0; j < 8; j++) acc[i][j] = 0.f;

    for (int k0 = 0; k0 < K; k0 += 8) {
        float4 av, bv;
        if (SRC == 2) {
            int kk = k0 + aCol;
            av = (kk < HH) ? *(const float4*)(Arow0 + kk)
                           : *(const float4*)(Arow1 + kk - HH);
        } else {
            av = *(const float4*)(Arow0 + k0 + aCol);
        }
        bv = *(const float4*)(Brow + k0 + aCol);

        __syncthreads();
        As[aCol + 0][aRow] = av.x; As[aCol + 1][aRow] = av.y;
        As[aCol + 2][aRow] = av.z; As[aCol + 3][aRow] = av.w;
        Bs[aCol + 0][aRow] = bv.x; Bs[aCol + 1][aRow] = bv.y;
        Bs[aCol + 2][aRow] = bv.z; Bs[aCol + 3][aRow] = bv.w;
        __syncthreads();

#pragma unroll
        for (int kk = 0; kk < 8; kk++) {
            float a[8], b[8];
            *(float4*)&a[0] = *(const float4*)&As[kk][ty * 8];
            *(float4*)&a[4] = *(const float4*)&As[kk][ty * 8 + 4];
            *(float4*)&b[0] = *(const float4*)&Bs[kk][tx * 8];
            *(float4*)&b[4] = *(const float4*)&Bs[kk][tx * 8 + 4];
#pragma unroll
            for (int i = 0; i < 8; i++)
#pragma unroll
                for (int j = 0; j < 8; j++) acc[i][j] = fmaf(a[i], b[j], acc[i][j]);
        }
    }

#pragma unroll
    for (int i = 0; i < 8; i++) {
        size_t m = (size_t)(m0 + ty * 8 + i);
        float* crow = C + m * (size_t)N + n0 + tx * 8;
#pragma unroll
        for (int j = 0; j < 8; j++) {
            int n = n0 + tx * 8 + j;
            float v = acc[i][j] + bias[n];
            if (bias2) v += bias2[n];
            if (TANH) v = tanhf(v);
            crow[j] = v;
        }
    }
}

// ---------------- LSTM scan: weights register-resident ----------------
__device__ __forceinline__ float sigm(float x) { return 1.f / (1.f + expf(-x)); }

__global__ void __launch_bounds__(1024, 1) lstm_scan(
    const float* __restrict__ h0, const float* __restrict__ c0,
    const float* __restrict__ Whh)
{
    __shared__ float h_s[HH];
    __shared__ float c_s[16];
    __shared__ float red[16][2][4];

    const int tid  = threadIdx.x;
    const int bx   = blockIdx.x;
    const int b    = bx >> 5;
    const int j0   = (bx & 31) * 16;
    const int u    = tid >> 6;           // unit 0..15
    const int lane = tid & 63;
    const int wu   = (tid >> 5) & 1;

    // register-resident weights: this thread's 8 k-slices x 4 gates
    float wr[4][8];
#pragma unroll
    for (int g = 0; g < 4; g++) {
        const float* wrow = Whh + ((size_t)(g * HH + j0 + u)) * HH;
#pragma unroll
        for (int i = 0; i < 8; i++) wr[g][i] = wrow[lane + i * 64];
    }
    if (tid < 16) c_s[tid] = c0[b * HH + j0 + tid];
    __syncthreads();

    for (int t = 0; t < TT; t++) {
        float xgi = 0.f, xgf = 0.f, xgg = 0.f, xgo = 0.f;
        if (tid < 16) {
            const float* xp = g_xg + ((size_t)(b * TT + t)) * FH + j0 + tid;
            xgi = xp[0]; xgf = xp[HH]; xgg = xp[2 * HH]; xgo = xp[3 * HH];
        }
        if (tid < HH) {
            h_s[tid] = (t == 0) ? h0[b * HH + tid]
                                : __ldcg(&g_hbuf[(t & 1) * BB * HH + b * HH + tid]);
        }
        __syncthreads();

        float ai = 0.f, af = 0.f, ag = 0.f, ao = 0.f;
#pragma unroll
        for (int i = 0; i < 8; i++) {
            float hv = h_s[lane + i * 64];
            ai = fmaf(hv, wr[0][i], ai);
            af = fmaf(hv, wr[1][i], af);
            ag = fmaf(hv, wr[2][i], ag);
            ao = fmaf(hv, wr[3][i], ao);
        }
#pragma unroll
        for (int off = 16; off > 0; off >>= 1) {
            ai += __shfl_down_sync(0xffffffffu, ai, off);
            af += __shfl_down_sync(0xffffffffu, af, off);
            ag += __shfl_down_sync(0xffffffffu, ag, off);
            ao += __shfl_down_sync(0xffffffffu, ao, off);
        }
        if ((tid & 31) == 0) {
            red[u][wu][0] = ai; red[u][wu][1] = af;
            red[u][wu][2] = ag; red[u][wu][3] = ao;
        }
        __syncthreads();

        if (tid < 16) {
            int uu = tid;
            float gi = xgi + red[uu][0][0] + red[uu][1][0];
            float gf = xgf + red[uu][0][1] + red[uu][1][1];
            float gG = xgg + red[uu][0][2] + red[uu][1][2];
            float go = xgo + red[uu][0][3] + red[uu][1][3];
            float c  = c_s[uu];
            c = sigm(gf) * c + sigm(gi) * tanhf(gG);
            float h = sigm(go) * tanhf(c);
            c_s[uu] = c;
            int j = j0 + uu;
            g_hbuf[((t + 1) & 1) * BB * HH + b * HH + j] = h;
            g_enc[((size_t)(b * TT + t)) * HH + j] = h;
        }
        __syncthreads();

        if (tid == 0) {
            unsigned my = *(volatile unsigned*)&g_bargen;
            __threadfence();
            unsigned arr = atomicAdd(&g_barcnt, 1u);
            if (arr == gridDim.x - 1) {
                g_barcnt = 0;
                __threadfence();
                atomicAdd(&g_bargen, 1u);
            } else {
                while (*(volatile unsigned*)&g_bargen == my) { }
            }
        }
        __syncthreads();
    }
}

// ---------------- s[m] = dot(g_tmp[m,:], wa2) + ba2 ----------------
__global__ void rowdot(const float* __restrict__ wa2, const float* __restrict__ ba2)
{
    int warp = threadIdx.x >> 5, lane = threadIdx.x & 31;
    int m = blockIdx.x * 8 + warp;
    const float* row = g_tmp + (size_t)m * HH;
    float acc = 0.f;
#pragma unroll
    for (int i = 0; i < 16; i++) acc = fmaf(row[lane + i * 32], wa2[lane + i * 32], acc);
#pragma unroll
    for (int off = 16; off > 0; off >>= 1) acc += __shfl_down_sync(0xffffffffu, acc, off);
    if (lane == 0) g_s[m] = acc + ba2[0];
}

// ---------------- per-batch softmax prefix prep ----------------
__global__ void __launch_bounds__(1024) softprep()
{
    __shared__ float p0[1024];
    __shared__ float p1[1024];
    int b = blockIdx.x, t = threadIdx.x;
    float s0 = g_s[b * TT + 2 * t], s1 = g_s[b * TT + 2 * t + 1];

    p0[t] = fmaxf(s0, s1);
    __syncthreads();
    for (int off = 512; off > 0; off >>= 1) {
        if (t < off) p0[t] = fmaxf(p0[t], p0[t + off]);
        __syncthreads();
    }
    float mx = p0[0];
    __syncthreads();

    float e0 = expf(s0 - mx), e1 = expf(s1 - mx);
    float p = e0 + e1;
    p0[t] = p;
    __syncthreads();

    float* src = p0; float* dst = p1;
    for (int off = 1; off < 1024; off <<= 1) {
        float v = src[t];
        if (t >= off) v += src[t - off];
        dst[t] = v;
        __syncthreads();
        float* tm = src; src = dst; dst = tm;
    }
    float incl = src[t];
    float excl = incl - p;
    g_e[b * TT + 2 * t]     = e0;
    g_e[b * TT + 2 * t + 1] = e1;
    g_rden[b * TT + 2 * t]     = 1.f / (excl + e0);
    g_rden[b * TT + 2 * t + 1] = 1.f / incl;
}

// ---------------- ctx two-phase chunked scan ----------------
__global__ void ctx_part()
{
    int id = blockIdx.x * blockDim.x + threadIdx.x;
    int b = id >> 14;
    int c = (id >> 9) & 31;
    int h = id & 511;
    const float* ep = g_e + b * TT + c * 64;
    const float* er = g_enc + (size_t)b * TT * HH + (size_t)(c * 64) * HH + h;
    float s = 0.f;
#pragma unroll 4
    for (int t = 0; t < 64; t++) s = fmaf(ep[t], er[(size_t)t * HH], s);
    g_part[(b * 32 + c) * HH + h] = s;
}
__global__ void ctx_main()
{
    int id = blockIdx.x * blockDim.x + threadIdx.x;
    int b = id >> 14;
    int c = (id >> 9) & 31;
    int h = id & 511;
    float base = 0.f;
    for (int cc = 0; cc < c; cc++) base += g_part[(b * 32 + cc) * HH + h];
    const float* ep = g_e + b * TT + c * 64;
    const float* rp = g_rden + b * TT + c * 64;
    const float* er = g_enc + (size_t)b * TT * HH + (size_t)(c * 64) * HH + h;
    float* cr = g_ctx + (size_t)b * TT * HH + (size_t)(c * 64) * HH + h;
    float num = base;
    for (int t = 0; t < 64; t++) {
        num = fmaf(ep[t], er[(size_t)t * HH], num);
        cr[(size_t)t * HH] = num * rp[t];
    }
}

// ---------------- launch ----------------
extern "C" void kernel_launch(void* const* d_in, const int* in_sizes, int n_in,
                              void* d_out, int out_size)
{
    const int*   input = (const int*)  d_in[0];
    const float* h0    = (const float*)d_in[1];
    const float* c0    = (const float*)d_in[2];
    const float* emb   = (const float*)d_in[3];
    const float* W_ih  = (const float*)d_in[4];
    const float* W_hh  = (const float*)d_in[5];
    const float* b_ih  = (const float*)d_in[6];
    const float* b_hh  = (const float*)d_in[7];
    const float* Wa1   = (const float*)d_in[8];
    const float* ba1   = (const float*)d_in[9];
    const float* wa2   = (const float*)d_in[10];
    const float* ba2   = (const float*)d_in[11];
    const float* Wc    = (const float*)d_in[12];
    const float* bc    = (const float*)d_in[13];
    const float* b_dec = (const float*)d_in[14];
    float* out = (float*)d_out;

    cudaFuncSetAttribute(dec_gemm, cudaFuncAttributeMaxDynamicSharedMemorySize, 2 * DS_STAGE_B);

    dim3 blk(256);

    to_half<0><<<(VV * HH + 255) / 256, 256>>>(emb, VV * HH);

    gemm128<0, 0, false><<<dim3(FH / 128, MROWS / 128), blk>>>(
        emb, input, W_ih, b_ih, b_hh, MROWS, FH, HH);

    lstm_scan<<<128, 1024>>>(h0, c0, W_hh);

    gemm128<1, 1, true><<<dim3(HH / 128, MROWS / 128), blk>>>(
        nullptr, nullptr, Wa1, ba1, nullptr, MROWS, HH, HH);
    rowdot<<<1024, 256>>>(wa2, ba2);

    softprep<<<BB, 1024>>>();
    ctx_part<<<256, 256>>>();
    ctx_main<<<256, 256>>>();

    gemm128<2, 2, true><<<dim3(HH / 128, MROWS / 128), blk>>>(
        nullptr, nullptr, Wc, bc, nullptr, MROWS, HH, 2 * HH);

    to_half<1><<<(MROWS * HH + 255) / 256, 256>>>(nullptr, MROWS * HH);

    dec_gemm<<<dim3(VV / 128, MROWS / 128), blk, 2 * DS_STAGE_B>>>(b_dec, out, VV);
}

// round 17
// speedup vs baseline: 2.3010x; 1.1437x over previous
#include <cuda_runtime.h>
#include <cuda_fp16.h>
#include <cstdint>
#include <math.h>

#define BB 4
#define TT 2048
#define HH 512
#define VV 32000
#define FH 2048
#define MROWS 8192

// ---------------- scratch (static device allocations; no cudaMalloc) ----------------
__device__ float g_xg[(size_t)MROWS * FH];
__device__ float g_enc[(size_t)MROWS * HH];
__device__ float g_tmp[(size_t)MROWS * HH];
__device__ float g_hbuf[2 * BB * HH];
__device__ float g_s[MROWS];
__device__ float g_e[MROWS];
__device__ float g_rden[MROWS];
__device__ float g_part[BB * 32 * HH];
__device__ unsigned g_bcnt[4 * 32];
__device__ unsigned g_bgen[4 * 32];

__device__ __align__(16) __half g_emb_h[(size_t)VV * HH];
__device__ __align__(16) __half g_comb_h[(size_t)MROWS * HH];
__device__ __align__(16) __half g_enc_h[(size_t)MROWS * HH];
__device__ __align__(16) __half g_ctx_h[(size_t)MROWS * HH];
__device__ __align__(16) __half g_wih_h[(size_t)FH * HH];
__device__ __align__(16) __half g_wa1_h[(size_t)HH * HH];
__device__ __align__(16) __half g_wc_h[(size_t)HH * 2 * HH];

// ---------------- helpers ----------------
__device__ __forceinline__ uint32_t s2u(const void* p) {
    uint32_t a;
    asm("{ .reg .u64 t; cvta.to.shared.u64 t, %1; cvt.u32.u64 %0, t; }" : "=r"(a) : "l"(p));
    return a;
}
__device__ __forceinline__ void mma16816h(float* c, const uint32_t* a, const uint32_t* b)
{
    asm volatile("mma.sync.aligned.m16n8k16.row.col.f32.f16.f16.f32 {%0,%1,%2,%3}, {%4,%5,%6,%7}, {%8,%9}, {%0,%1,%2,%3};"
        : "+f"(c[0]), "+f"(c[1]), "+f"(c[2]), "+f"(c[3])
        : "r"(a[0]), "r"(a[1]), "r"(a[2]), "r"(a[3]), "r"(b[0]), "r"(b[1]));
}
__device__ __forceinline__ void ldmx4(uint32_t* r, uint32_t a) {
    asm volatile("ldmatrix.sync.aligned.m8n8.x4.shared.b16 {%0,%1,%2,%3}, [%4];"
        : "=r"(r[0]), "=r"(r[1]), "=r"(r[2]), "=r"(r[3]) : "r"(a));
}
__device__ __forceinline__ void cpasync16(uint32_t dst, const void* src) {
    asm volatile("cp.async.cg.shared.global [%0], [%1], 16;" :: "r"(dst), "l"(src));
}

// ---------------- fp32 -> fp16 converters (globals selected in-kernel) ----------------
template <int SEL>
__global__ void conv_h(const float* __restrict__ X, int n)
{
    __half* dst = (SEL == 0) ? g_emb_h : (SEL == 1) ? g_wih_h : (SEL == 2) ? g_wa1_h : g_wc_h;
    int i = blockIdx.x * blockDim.x + threadIdx.x;
    if (i < n) dst[i] = __float2half_rn(X[i]);
}

// ---------------- unified fp16 HMMA GEMM; all scratch globals resolved IN KERNEL ----------------
// MODE 0: xg  = emb[gidx] @ W_ih^T + b_ih + b_hh          -> g_xg   (fp32), N=FH, K=HH
// MODE 1: tmp = tanh(enc @ Wa1^T + ba1)                   -> g_tmp  (fp32), N=HH, K=HH
// MODE 2: comb= tanh(concat(ctx,enc) @ Wc^T + bc)         -> g_comb_h (fp16), N=HH, K=2HH
// MODE 3: out = comb @ emb^T + b_dec                      -> out    (fp32), N=VV, K=HH
// CTA 256 thr = 8 warps (4 M x 2 N), tile 128x128, warp tile 32x64, BK=32, cp.async 2-stage.

#define DS_STRIDE 40
#define DS_TILE   (128 * DS_STRIDE)
#define DS_TILE_B (DS_TILE * 2)
#define DS_STAGE_B (2 * DS_TILE_B)

template <int AM, int KB>
__device__ __forceinline__ void h_prefetch(uint32_t sbase, int buf, int tid, int m0, int n0, int kb,
    const __half* A0, const __half* A1, const __half* Bw, const int* s_tok)
{
    uint32_t dstb = sbase + (uint32_t)buf * DS_STAGE_B;
#pragma unroll
    for (int i = 0; i < 2; i++) {
        int u = tid + i * 256;
        int row = u >> 2, cu = u & 3;
        const __half* src;
        if (AM == 1) {
            src = A0 + (size_t)s_tok[row] * HH + kb + cu * 8;
        } else if (AM == 2) {
            src = (kb < HH) ? A0 + (size_t)(m0 + row) * HH + kb + cu * 8
                            : A1 + (size_t)(m0 + row) * HH + (kb - HH) + cu * 8;
        } else {
            src = A0 + (size_t)(m0 + row) * HH + kb + cu * 8;
        }
        cpasync16(dstb + (uint32_t)((row * DS_STRIDE + cu * 8) * 2), (const void*)src);
    }
#pragma unroll
    for (int i = 0; i < 2; i++) {
        int u = tid + i * 256;
        int row = u >> 2, cu = u & 3;
        const __half* src = Bw + (size_t)(n0 + row) * KB + kb + cu * 8;
        cpasync16(dstb + (uint32_t)DS_TILE_B + (uint32_t)((row * DS_STRIDE + cu * 8) * 2), (const void*)src);
    }
    asm volatile("cp.async.commit_group;" ::: "memory");
}

__device__ __forceinline__ void h_compute_stage(uint32_t sb, int warp_m, int warp_n,
                                                int lane, float acc[2][8][4])
{
    const int arow = warp_m * 32 + 8 * ((lane >> 3) & 1) + (lane & 7);
    const int brow = warp_n * 64 + 8 * (lane >> 4) + (lane & 7);
#pragma unroll
    for (int ks = 0; ks < 2; ks++) {
        const int acol = ks * 16 + 8 * (lane >> 4);
        const int bcol = ks * 16 + 8 * ((lane >> 3) & 1);
        uint32_t ah[2][4];
#pragma unroll
        for (int mf = 0; mf < 2; mf++) {
            uint32_t ra = sb + (uint32_t)(((arow + mf * 16) * DS_STRIDE + acol) * 2);
            ldmx4(ah[mf], ra);
        }
#pragma unroll
        for (int nfp = 0; nfp < 4; nfp++) {
            uint32_t rb = sb + (uint32_t)DS_TILE_B
                        + (uint32_t)(((brow + nfp * 16) * DS_STRIDE + bcol) * 2);
            uint32_t bh[4];
            ldmx4(bh, rb);
#pragma unroll
            for (int mf = 0; mf < 2; mf++) {
                mma16816h(acc[mf][2 * nfp + 0], ah[mf], bh + 0);
                mma16816h(acc[mf][2 * nfp + 1], ah[mf], bh + 2);
            }
        }
    }
}

template <int MODE>
__global__ void __launch_bounds__(256, 2) hgemm(
    const int* __restrict__ gidx,
    const float* __restrict__ bias, const float* __restrict__ bias2,
    float* __restrict__ out)
{
    extern __shared__ __half ds[];
    __shared__ int s_tok[128];

    constexpr int  AM   = (MODE == 0) ? 1 : (MODE == 2) ? 2 : 0;
    constexpr bool TANH = (MODE == 1 || MODE == 2);
    constexpr bool OUTH = (MODE == 2);
    constexpr bool B2   = (MODE == 0);
    constexpr int  KB   = (MODE == 2) ? 2 * HH : HH;
    const int NN = (MODE == 0) ? FH : (MODE == 3) ? VV : HH;

    const __half* A0 = (MODE == 0) ? g_emb_h : (MODE == 1) ? g_enc_h
                     : (MODE == 2) ? g_ctx_h : g_comb_h;
    const __half* A1 = g_enc_h;
    const __half* Bw = (MODE == 0) ? g_wih_h : (MODE == 1) ? g_wa1_h
                     : (MODE == 2) ? g_wc_h  : g_emb_h;
    float* C = (MODE == 0) ? g_xg : (MODE == 1) ? g_tmp : out;
    __half* Ch = g_comb_h;

    const int tid = threadIdx.x;
    const int wid = tid >> 5;
    const int lane = tid & 31;
    const int gr = lane >> 2;
    const int tg = lane & 3;
    const int warp_m = wid & 3;
    const int warp_n = wid >> 2;
    const int m0 = blockIdx.y * 128;
    const int n0 = blockIdx.x * 128;
    const uint32_t sbase = s2u(ds);

    if (AM == 1) {
        if (tid < 128) s_tok[tid] = gidx[m0 + tid];
        __syncthreads();
    }

    float acc[2][8][4];
#pragma unroll
    for (int mf = 0; mf < 2; mf++)
#pragma unroll
        for (int nf = 0; nf < 8; nf++)
#pragma unroll
            for (int i = 0; i < 4; i++) acc[mf][nf][i] = 0.f;

    constexpr int nch = KB / 32;
    h_prefetch<AM, KB>(sbase, 0, tid, m0, n0, 0, A0, A1, Bw, s_tok);

    for (int c = 0; c < nch; c++) {
        if (c + 1 < nch) {
            h_prefetch<AM, KB>(sbase, (c + 1) & 1, tid, m0, n0, (c + 1) * 32, A0, A1, Bw, s_tok);
            asm volatile("cp.async.wait_group 1;" ::: "memory");
        } else {
            asm volatile("cp.async.wait_group 0;" ::: "memory");
        }
        __syncthreads();
        h_compute_stage(sbase + (uint32_t)(c & 1) * DS_STAGE_B, warp_m, warp_n, lane, acc);
        __syncthreads();
    }

    float2 bv[8], bv2[8];
#pragma unroll
    for (int nf = 0; nf < 8; nf++) {
        int n = n0 + warp_n * 64 + nf * 8 + 2 * tg;
        bv[nf] = *(const float2*)(bias + n);
        if (B2) bv2[nf] = *(const float2*)(bias2 + n);
    }
#pragma unroll
    for (int mf = 0; mf < 2; mf++) {
        int m = m0 + warp_m * 32 + mf * 16 + gr;
#pragma unroll
        for (int nf = 0; nf < 8; nf++) {
            int n = n0 + warp_n * 64 + nf * 8 + 2 * tg;
            float v0x = acc[mf][nf][0] + bv[nf].x;
            float v0y = acc[mf][nf][1] + bv[nf].y;
            float v1x = acc[mf][nf][2] + bv[nf].x;
            float v1y = acc[mf][nf][3] + bv[nf].y;
            if (B2) { v0x += bv2[nf].x; v0y += bv2[nf].y; v1x += bv2[nf].x; v1y += bv2[nf].y; }
            if (TANH) { v0x = tanhf(v0x); v0y = tanhf(v0y); v1x = tanhf(v1x); v1y = tanhf(v1y); }
            if (OUTH) {
                *(__half2*)(Ch + (size_t)m * NN + n) = __floats2half2_rn(v0x, v0y);
                *(__half2*)(Ch + (size_t)(m + 8) * NN + n) = __floats2half2_rn(v1x, v1y);
            } else {
                float2 o0; o0.x = v0x; o0.y = v0y;
                float2 o1; o1.x = v1x; o1.y = v1y;
                *(float2*)(C + (size_t)m * NN + n) = o0;
                *(float2*)(C + (size_t)(m + 8) * NN + n) = o1;
            }
        }
    }
}

// ---------------- LSTM scan: 1 warp per unit, per-batch barrier ----------------
__device__ __forceinline__ float sigm(float x) { return 1.f / (1.f + expf(-x)); }

__global__ void __launch_bounds__(512, 1) lstm_scan(
    const float* __restrict__ h0, const float* __restrict__ c0,
    const float* __restrict__ Whh)
{
    __shared__ float h_s[HH];
    __shared__ float xg_s[64];
    __shared__ float c_s[16];

    const int tid  = threadIdx.x;
    const int bx   = blockIdx.x;
    const int b    = bx >> 5;
    const int j0   = (bx & 31) * 16;
    const int w    = tid >> 5;           // warp = unit 0..15
    const int lane = tid & 31;

    float wr[4][16];
#pragma unroll
    for (int g = 0; g < 4; g++) {
        const float* wrow = Whh + ((size_t)(g * HH + j0 + w)) * HH;
#pragma unroll
        for (int i = 0; i < 16; i++) wr[g][i] = wrow[lane + i * 32];
    }
    if (tid < 16) c_s[tid] = c0[b * HH + j0 + tid];
    __syncthreads();

    unsigned* cnt = &g_bcnt[b * 32];
    unsigned* gen = &g_bgen[b * 32];

    for (int t = 0; t < TT; t++) {
        if (tid < 64) {
            int g = tid >> 4, uu = tid & 15;
            xg_s[tid] = g_xg[((size_t)(b * TT + t)) * FH + g * HH + j0 + uu];
        }
        h_s[tid] = (t == 0) ? h0[b * HH + tid]
                            : __ldcg(&g_hbuf[(t & 1) * BB * HH + b * HH + tid]);
        __syncthreads();

        float a0 = 0.f, a1 = 0.f, a2 = 0.f, a3 = 0.f;
#pragma unroll
        for (int i = 0; i < 16; i++) {
            float hv = h_s[lane + i * 32];
            a0 = fmaf(hv, wr[0][i], a0);
            a1 = fmaf(hv, wr[1][i], a1);
            a2 = fmaf(hv, wr[2][i], a2);
            a3 = fmaf(hv, wr[3][i], a3);
        }
#pragma unroll
        for (int off = 16; off > 0; off >>= 1) {
            a0 += __shfl_down_sync(0xffffffffu, a0, off);
            a1 += __shfl_down_sync(0xffffffffu, a1, off);
            a2 += __shfl_down_sync(0xffffffffu, a2, off);
            a3 += __shfl_down_sync(0xffffffffu, a3, off);
        }
        if (lane == 0) {
            float gi = xg_s[w]      + a0;
            float gf = xg_s[16 + w] + a1;
            float gG = xg_s[32 + w] + a2;
            float go = xg_s[48 + w] + a3;
            float c  = c_s[w];
            c = sigm(gf) * c + sigm(gi) * tanhf(gG);
            float h = sigm(go) * tanhf(c);
            c_s[w] = c;
            int j = j0 + w;
            g_hbuf[((t + 1) & 1) * BB * HH + b * HH + j] = h;
            g_enc[((size_t)(b * TT + t)) * HH + j] = h;
            g_enc_h[((size_t)(b * TT + t)) * HH + j] = __float2half_rn(h);
        }
        __syncthreads();

        if (t + 1 < TT) {
            if (tid == 0) {
                unsigned my = *(volatile unsigned*)gen;
                __threadfence();
                unsigned arr = atomicAdd(cnt, 1u);
                if (arr == 31u) {
                    *cnt = 0;
                    __threadfence();
                    atomicAdd(gen, 1u);
                } else {
                    while (*(volatile unsigned*)gen == my) { }
                }
            }
            __syncthreads();
        }
    }
}

// ---------------- s[m] = dot(g_tmp[m,:], wa2) + ba2 ----------------
__global__ void rowdot(const float* __restrict__ wa2, const float* __restrict__ ba2)
{
    int warp = threadIdx.x >> 5, lane = threadIdx.x & 31;
    int m = blockIdx.x * 8 + warp;
    const float* row = g_tmp + (size_t)m * HH;
    float acc = 0.f;
#pragma unroll
    for (int i = 0; i < 16; i++) acc = fmaf(row[lane + i * 32], wa2[lane + i * 32], acc);
#pragma unroll
    for (int off = 16; off > 0; off >>= 1) acc += __shfl_down_sync(0xffffffffu, acc, off);
    if (lane == 0) g_s[m] = acc + ba2[0];
}

// ---------------- per-batch softmax prefix prep ----------------
__global__ void __launch_bounds__(1024) softprep()
{
    __shared__ float p0[1024];
    __shared__ float p1[1024];
    int b = blockIdx.x, t = threadIdx.x;
    float s0 = g_s[b * TT + 2 * t], s1 = g_s[b * TT + 2 * t + 1];

    p0[t] = fmaxf(s0, s1);
    __syncthreads();
    for (int off = 512; off > 0; off >>= 1) {
        if (t < off) p0[t] = fmaxf(p0[t], p0[t + off]);
        __syncthreads();
    }
    float mx = p0[0];
    __syncthreads();

    float e0 = expf(s0 - mx), e1 = expf(s1 - mx);
    float p = e0 + e1;
    p0[t] = p;
    __syncthreads();

    float* src = p0; float* dst = p1;
    for (int off = 1; off < 1024; off <<= 1) {
        float v = src[t];
        if (t >= off) v += src[t - off];
        dst[t] = v;
        __syncthreads();
        float* tm = src; src = dst; dst = tm;
    }
    float incl = src[t];
    float excl = incl - p;
    g_e[b * TT + 2 * t]     = e0;
    g_e[b * TT + 2 * t + 1] = e1;
    g_rden[b * TT + 2 * t]     = 1.f / (excl + e0);
    g_rden[b * TT + 2 * t + 1] = 1.f / incl;
}

// ---------------- ctx two-phase chunked scan (fp16 output) ----------------
__global__ void ctx_part()
{
    int id = blockIdx.x * blockDim.x + threadIdx.x;
    int b = id >> 14;
    int c = (id >> 9) & 31;
    int h = id & 511;
    const float* ep = g_e + b * TT + c * 64;
    const float* er = g_enc + (size_t)b * TT * HH + (size_t)(c * 64) * HH + h;
    float s = 0.f;
#pragma unroll 4
    for (int t = 0; t < 64; t++) s = fmaf(ep[t], er[(size_t)t * HH], s);
    g_part[(b * 32 + c) * HH + h] = s;
}
__global__ void ctx_main()
{
    int id = blockIdx.x * blockDim.x + threadIdx.x;
    int b = id >> 14;
    int c = (id >> 9) & 31;
    int h = id & 511;
    float base = 0.f;
    for (int cc = 0; cc < c; cc++) base += g_part[(b * 32 + cc) * HH + h];
    const float* ep = g_e + b * TT + c * 64;
    const float* rp = g_rden + b * TT + c * 64;
    const float* er = g_enc + (size_t)b * TT * HH + (size_t)(c * 64) * HH + h;
    __half* cr = g_ctx_h + (size_t)b * TT * HH + (size_t)(c * 64) * HH + h;
    float num = base;
    for (int t = 0; t < 64; t++) {
        num = fmaf(ep[t], er[(size_t)t * HH], num);
        cr[(size_t)t * HH] = __float2half_rn(num * rp[t]);
    }
}

// ---------------- launch ----------------
extern "C" void kernel_launch(void* const* d_in, const int* in_sizes, int n_in,
                              void* d_out, int out_size)
{
    const int*   input = (const int*)  d_in[0];
    const float* h0    = (const float*)d_in[1];
    const float* c0    = (const float*)d_in[2];
    const float* emb   = (const float*)d_in[3];
    const float* W_ih  = (const float*)d_in[4];
    const float* W_hh  = (const float*)d_in[5];
    const float* b_ih  = (const float*)d_in[6];
    const float* b_hh  = (const float*)d_in[7];
    const float* Wa1   = (const float*)d_in[8];
    const float* ba1   = (const float*)d_in[9];
    const float* wa2   = (const float*)d_in[10];
    const float* ba2   = (const float*)d_in[11];
    const float* Wc    = (const float*)d_in[12];
    const float* bc    = (const float*)d_in[13];
    const float* b_dec = (const float*)d_in[14];
    float* out = (float*)d_out;

    dim3 blk(256);

    // converters (fp32 harness inputs -> fp16 device globals)
    conv_h<0><<<(VV * HH + 255) / 256, 256>>>(emb, VV * HH);
    conv_h<1><<<(FH * HH + 255) / 256, 256>>>(W_ih, FH * HH);
    conv_h<2><<<(HH * HH + 255) / 256, 256>>>(Wa1, HH * HH);
    conv_h<3><<<(HH * 2 * HH + 255) / 256, 256>>>(Wc, HH * 2 * HH);

    // 1) xg = emb[input] @ W_ih^T + (b_ih + b_hh)
    hgemm<0><<<dim3(FH / 128, MROWS / 128), blk, 2 * DS_STAGE_B>>>(input, b_ih, b_hh, nullptr);

    // 2) LSTM scan
    lstm_scan<<<128, 512>>>(h0, c0, W_hh);

    // 3) tmp = tanh(enc @ Wa1^T + ba1) ; s = tmp @ wa2 + ba2
    hgemm<1><<<dim3(HH / 128, MROWS / 128), blk, 2 * DS_STAGE_B>>>(nullptr, ba1, nullptr, nullptr);
    rowdot<<<1024, 256>>>(wa2, ba2);

    // 4) softmax prefix pooling
    softprep<<<BB, 1024>>>();
    ctx_part<<<256, 256>>>();
    ctx_main<<<256, 256>>>();

    // 5) combined = tanh(concat(ctx, enc) @ Wc^T + bc)  [fp16 out -> g_comb_h]
    hgemm<2><<<dim3(HH / 128, MROWS / 128), blk, 2 * DS_STAGE_B>>>(nullptr, bc, nullptr, nullptr);

    // 6) decoded = combined @ emb^T + b_dec
    hgemm<3><<<dim3(VV / 128, MROWS / 128), blk, 2 * DS_STAGE_B>>>(nullptr, b_dec, nullptr, out);
}